// round 2
// baseline (speedup 1.0000x reference)
#include <cuda_runtime.h>
#include <math.h>

#define BATCH 16
#define NCLASS 10

// ---------------- scratch (static __device__, allocation-free) ----------------
__device__ float g_Whz[(size_t)BATCH * 1024 * 256];   // 16 MB
__device__ float g_Whs[(size_t)BATCH * 1024 * 64];    // 4 MB
__device__ float g_Zb [(size_t)BATCH * 1024 * 256];   // 16 MB
__device__ float g_Sb [(size_t)BATCH * 1024 * 64];    // 4 MB
__device__ float g_att[(size_t)BATCH * 1024 * 1024];  // 64 MB
__device__ float g_Tb [(size_t)BATCH * 64 * 1024];    // 4 MB
__device__ float g_Gb [(size_t)BATCH * 64 * 64];
__device__ float g_Xp [(size_t)BATCH * 64 * 256];
__device__ float g_Ap [(size_t)BATCH * 64 * 64];
__device__ float g_Xq [(size_t)BATCH * 8 * 256];
__device__ float g_Aq [(size_t)BATCH * 8 * 8];
__device__ float g_X3 [(size_t)BATCH * 256];
__device__ float g_A3 [(size_t)BATCH];
__device__ float g_f1z[BATCH * 1024];
__device__ float g_f2z[BATCH * 1024];
__device__ float g_f1s[BATCH * 1024];
__device__ float g_f2s[BATCH * 1024];
__device__ double g_link, g_ent, g_tot;

// ---------------- generic tiled GEMM ----------------
// C[b] = op(A[b]) * B[b], fp32, optional ReLU epilogue.
// !TA: A is M x K row-major.  TA: A is stored K x M row-major (we compute A^T * B).
template<int BM, int BN, int BK, int TM, int TN, bool TA, bool RELU>
__global__ __launch_bounds__((BM / TM) * (BN / TN))
void gemm_k(const float* __restrict__ Ag, const float* __restrict__ Bg,
            float* __restrict__ Cg, int M, int N, int K,
            long sA, long sB, long sC)
{
    constexpr int THREADS = (BM / TM) * (BN / TN);
    const float* Ab = Ag + (long)blockIdx.z * sA;
    const float* Bb = Bg + (long)blockIdx.z * sB;
    float* Cb = Cg + (long)blockIdx.z * sC;
    __shared__ float As[BK][BM + 4];
    __shared__ float Bs[BK][BN + 4];
    const int bm = blockIdx.y * BM, bn = blockIdx.x * BN;
    const int tid = threadIdx.x;
    constexpr int TCOLS = BN / TN;
    const int tx = tid % TCOLS, ty = tid / TCOLS;
    float acc[TM][TN];
#pragma unroll
    for (int i = 0; i < TM; i++)
#pragma unroll
        for (int j = 0; j < TN; j++) acc[i][j] = 0.f;

    for (int k0 = 0; k0 < K; k0 += BK) {
        if (!TA) {
            for (int idx = tid; idx < BM * BK; idx += THREADS) {
                int kk = idx % BK, m = idx / BK;
                int gm = bm + m, gk = k0 + kk;
                As[kk][m] = (gm < M && gk < K) ? Ab[(long)gm * K + gk] : 0.f;
            }
        } else {
            for (int idx = tid; idx < BM * BK; idx += THREADS) {
                int m = idx % BM, kk = idx / BM;
                int gm = bm + m, gk = k0 + kk;
                As[kk][m] = (gm < M && gk < K) ? Ab[(long)gk * M + gm] : 0.f;
            }
        }
        for (int idx = tid; idx < BK * BN; idx += THREADS) {
            int n = idx % BN, kk = idx / BN;
            int gn = bn + n, gk = k0 + kk;
            Bs[kk][n] = (gn < N && gk < K) ? Bb[(long)gk * N + gn] : 0.f;
        }
        __syncthreads();
#pragma unroll
        for (int kk = 0; kk < BK; kk++) {
            float ra[TM], rb[TN];
#pragma unroll
            for (int i = 0; i < TM; i++) ra[i] = As[kk][ty * TM + i];
#pragma unroll
            for (int j = 0; j < TN; j++) rb[j] = Bs[kk][tx * TN + j];
#pragma unroll
            for (int i = 0; i < TM; i++)
#pragma unroll
                for (int j = 0; j < TN; j++) acc[i][j] += ra[i] * rb[j];
        }
        __syncthreads();
    }
#pragma unroll
    for (int i = 0; i < TM; i++) {
        int gm = bm + ty * TM + i;
        if (gm >= M) continue;
#pragma unroll
        for (int j = 0; j < TN; j++) {
            int gn = bn + tx * TN + j;
            if (gn >= N) continue;
            float v = acc[i][j];
            if (RELU) v = v > 0.f ? v : 0.f;
            Cb[(long)gm * N + gn] = v;
        }
    }
}

// ---------------- f1/f2 = Wh . a[:F], Wh . a[F:] (warp per row) ----------------
__global__ void fvec_k(const float* __restrict__ Wh, const float* __restrict__ a,
                       float* __restrict__ f1, float* __restrict__ f2,
                       int rows, int F)
{
    int w = (blockIdx.x * blockDim.x + threadIdx.x) >> 5;
    int lane = threadIdx.x & 31;
    if (w >= rows) return;
    const float* p = Wh + (size_t)w * F;
    float s1 = 0.f, s2 = 0.f;
    for (int f = lane; f < F; f += 32) {
        float v = p[f];
        s1 += v * a[f];
        s2 += v * a[F + f];
    }
#pragma unroll
    for (int o = 16; o > 0; o >>= 1) {
        s1 += __shfl_down_sync(0xffffffffu, s1, o);
        s2 += __shfl_down_sync(0xffffffffu, s2, o);
    }
    if (lane == 0) { f1[w] = s1; f2[w] = s2; }
}

// ---------------- masked-softmax attention row (block per row) ----------------
// att[b,i,j] = softmax_j( A[b,i,j]>0 ? leakyrelu(f1_i+f2_j,0.2) : -9e15 )
__global__ void att_softmax(const float* __restrict__ A, const float* __restrict__ f1,
                            const float* __restrict__ f2, float* __restrict__ att, int N)
{
    int row = blockIdx.x;          // b*N + i
    int b = row / N;
    const float* Ar = A + (size_t)row * N;
    const float* f2b = f2 + (size_t)b * N;
    float f1i = f1[row];
    int t = threadIdx.x;
    float ev[4];
    float m = -1e30f;
#pragma unroll
    for (int it = 0; it < 4; it++) {
        int j = t + it * 256;
        float e = -1e30f;
        if (j < N) {
            float x = f1i + f2b[j];
            e = (x > 0.f) ? x : 0.2f * x;
            if (!(Ar[j] > 0.f)) e = -9e15f;
        }
        ev[it] = e;
        m = fmaxf(m, e);
    }
    __shared__ float sh[256];
    sh[t] = m; __syncthreads();
    for (int s = 128; s > 0; s >>= 1) { if (t < s) sh[t] = fmaxf(sh[t], sh[t + s]); __syncthreads(); }
    m = sh[0];
    __syncthreads();
    float lsum = 0.f;
#pragma unroll
    for (int it = 0; it < 4; it++) {
        int j = t + it * 256;
        if (j < N) { ev[it] = __expf(ev[it] - m); lsum += ev[it]; }
    }
    sh[t] = lsum; __syncthreads();
    for (int s = 128; s > 0; s >>= 1) { if (t < s) sh[t] += sh[t + s]; __syncthreads(); }
    float inv = 1.f / sh[0];
    float* Or = att + (size_t)row * N;
#pragma unroll
    for (int it = 0; it < 4; it++) {
        int j = t + it * 256;
        if (j < N) Or[j] = ev[it] * inv;
    }
}

// ---------------- softmax over c (warp per row) + entropy accumulation ----------------
__global__ void softmax_c_ent(float* __restrict__ S, int rows, int c, double inv_rows)
{
    int w = (blockIdx.x * blockDim.x + threadIdx.x) >> 5;
    int lane = threadIdx.x & 31;
    if (w >= rows) return;
    float* p = S + (size_t)w * c;
    float v[2] = {-1e30f, -1e30f};
    float m = -1e30f;
#pragma unroll
    for (int i = 0; i < 2; i++) {
        int f = lane + 32 * i;
        if (f < c) { v[i] = p[f]; m = fmaxf(m, v[i]); }
    }
#pragma unroll
    for (int o = 16; o > 0; o >>= 1) m = fmaxf(m, __shfl_xor_sync(0xffffffffu, m, o));
    float s = 0.f;
#pragma unroll
    for (int i = 0; i < 2; i++) {
        int f = lane + 32 * i;
        if (f < c) { v[i] = __expf(v[i] - m); s += v[i]; }
    }
#pragma unroll
    for (int o = 16; o > 0; o >>= 1) s += __shfl_xor_sync(0xffffffffu, s, o);
    float inv = 1.f / s;
    double erow = 0.0;
#pragma unroll
    for (int i = 0; i < 2; i++) {
        int f = lane + 32 * i;
        if (f < c) {
            float q = v[i] * inv;
            p[f] = q;
            erow += -(double)q * (double)logf(q + 1e-15f);
        }
    }
#pragma unroll
    for (int o = 16; o > 0; o >>= 1) erow += __shfl_down_sync(0xffffffffu, erow, o);
    if (lane == 0) atomicAdd(&g_ent, erow * inv_rows);
}

// ---------------- loss reductions ----------------
__global__ void accum_sq(const float* __restrict__ x, long n)
{
    __shared__ double sh[256];
    long i = (long)blockIdx.x * blockDim.x + threadIdx.x;
    double s = 0.0;
    long stride = (long)gridDim.x * blockDim.x;
    for (; i < n; i += stride) { double v = x[i]; s += v * v; }
    sh[threadIdx.x] = s; __syncthreads();
    for (int r = 128; r > 0; r >>= 1) { if (threadIdx.x < r) sh[threadIdx.x] += sh[threadIdx.x + r]; __syncthreads(); }
    if (threadIdx.x == 0) atomicAdd(&g_tot, sh[0]);
}

__global__ void trace_neg2(const float* __restrict__ Anew, int total, int c)
{
    int t = blockIdx.x * blockDim.x + threadIdx.x;
    if (t >= total) return;
    int b = t / c, j = t % c;
    atomicAdd(&g_tot, -2.0 * (double)Anew[((long)b * c + j) * c + j]);
}

__global__ void k_zero_losses() { g_link = 0.0; g_ent = 0.0; g_tot = 0.0; }
__global__ void k_zero_tot()    { g_tot = 0.0; }
__global__ void k_finalize_link(double denom)
{
    double v = g_tot;
    g_link += sqrt(v > 0.0 ? v : 0.0) / denom;
}

// ---------------- final dense + output assembly ----------------
__global__ void final_logits(const float* __restrict__ X3, const float* __restrict__ Wd,
                             const float* __restrict__ bd, float* __restrict__ out, int out_size)
{
    int t = blockIdx.x * blockDim.x + threadIdx.x;
    if (t >= BATCH * NCLASS) return;
    int b = t / NCLASS, cls = t % NCLASS;
    float s = bd[cls];
    const float* xr = X3 + (long)b * 256;
    for (int f = 0; f < 256; f++) s += xr[f] * Wd[f * NCLASS + cls];
    if (t < out_size) out[t] = s;
}

__global__ void write_tail(const float* __restrict__ A3, float* __restrict__ out, int out_size)
{
    int t = threadIdx.x;
    if (t < BATCH && 160 + t < out_size) out[160 + t] = A3[t];
    if (t == 0) {
        if (176 < out_size) out[176] = (float)g_link;
        if (177 < out_size) out[177] = (float)g_ent;
    }
}

// ---------------- host-side dispatch helpers ----------------
static void gemm_nn_big(const float* A, const float* B, float* C, int M, int N, int K,
                        long sA, long sB, long sC, bool relu)
{
    dim3 g((N + 127) / 128, (M + 127) / 128, BATCH);
    if (relu) gemm_k<128, 128, 16, 8, 8, false, true ><<<g, 256>>>(A, B, C, M, N, K, sA, sB, sC);
    else      gemm_k<128, 128, 16, 8, 8, false, false><<<g, 256>>>(A, B, C, M, N, K, sA, sB, sC);
}
static void gemm_nn_n64(const float* A, const float* B, float* C, int M, int N, int K,
                        long sA, long sB, long sC, bool relu)
{
    dim3 g((N + 63) / 64, (M + 127) / 128, BATCH);
    if (relu) gemm_k<128, 64, 16, 8, 4, false, true ><<<g, 256>>>(A, B, C, M, N, K, sA, sB, sC);
    else      gemm_k<128, 64, 16, 8, 4, false, false><<<g, 256>>>(A, B, C, M, N, K, sA, sB, sC);
}
static void gemm_tn_m64(const float* A, const float* B, float* C, int M, int N, int K,
                        long sA, long sB, long sC)
{
    dim3 g((N + 127) / 128, (M + 63) / 64, BATCH);
    gemm_k<64, 128, 16, 4, 8, true, false><<<g, 256>>>(A, B, C, M, N, K, sA, sB, sC);
}
static void gemm_nn_64(const float* A, const float* B, float* C, int M, int N, int K,
                       long sA, long sB, long sC)
{
    dim3 g((N + 63) / 64, (M + 63) / 64, BATCH);
    gemm_k<64, 64, 16, 4, 4, false, false><<<g, 256>>>(A, B, C, M, N, K, sA, sB, sC);
}
static void gemm_tn_64(const float* A, const float* B, float* C, int M, int N, int K,
                       long sA, long sB, long sC)
{
    dim3 g((N + 63) / 64, (M + 63) / 64, BATCH);
    gemm_k<64, 64, 16, 4, 4, true, false><<<g, 256>>>(A, B, C, M, N, K, sA, sB, sC);
}

static int grid_for(long n) { long b = (n + 255) / 256; return (int)(b < 2048 ? b : 2048); }

// One GAT+pool layer.
static void run_layer(const float* X, const float* A,
                      const float* Wg, const float* ag, const float* Ws, const float* as_,
                      float* Xout, float* Aout,
                      int N, int Fin, int Fz, int c,
                      float* whz, float* whs, float* z, float* s, float* att, float* t, float* gg,
                      float* f1z, float* f2z, float* f1s, float* f2s)
{
    int rows = BATCH * N;
    long sX = (long)N * Fin;

    gemm_nn_big(X, Wg, whz, N, Fz, Fin, sX, 0, (long)N * Fz, false);
    gemm_nn_n64(X, Ws, whs, N, c, Fin, sX, 0, (long)N * c, false);

    int fblocks = (rows * 32 + 255) / 256;
    fvec_k<<<fblocks, 256>>>(whz, ag, f1z, f2z, rows, Fz);
    fvec_k<<<fblocks, 256>>>(whs, as_, f1s, f2s, rows, c);

    // Z = relu(att_z @ Wh_z)
    att_softmax<<<rows, 256>>>(A, f1z, f2z, att, N);
    gemm_nn_big(att, whz, z, N, Fz, N, (long)N * N, (long)N * Fz, (long)N * Fz, true);

    // S_pre = relu(att_s @ Wh_s), then softmax over c + entropy
    att_softmax<<<rows, 256>>>(A, f1s, f2s, att, N);
    gemm_nn_n64(att, whs, s, N, c, N, (long)N * N, (long)N * c, (long)N * c, true);
    softmax_c_ent<<<(rows + 7) / 8, 256>>>(s, rows, c, 1.0 / (double)rows);

    // T = S^T A ;  A_new = T S ;  X_new = S^T Z ;  G = S^T S
    gemm_tn_m64(s, A, t, c, N, N, (long)N * c, (long)N * N, (long)c * N);
    gemm_nn_64(t, s, Aout, c, c, N, (long)c * N, (long)N * c, (long)c * c);
    gemm_tn_m64(s, z, Xout, c, Fz, N, (long)N * c, (long)N * Fz, (long)c * Fz);
    gemm_tn_64(s, s, gg, c, c, N, (long)N * c, (long)N * c, (long)c * c);

    // link loss: ||A - S S^T||_F^2 = sum(A^2) - 2 tr(S^T A S) + ||S^T S||_F^2
    k_zero_tot<<<1, 1>>>();
    long nA = (long)BATCH * N * N;
    accum_sq<<<grid_for(nA), 256>>>(A, nA);
    trace_neg2<<<(BATCH * c + 255) / 256, 256>>>(Aout, BATCH * c, c);
    long nG = (long)BATCH * c * c;
    accum_sq<<<grid_for(nG), 256>>>(gg, nG);
    k_finalize_link<<<1, 1>>>((double)nA);
}

extern "C" void kernel_launch(void* const* d_in, const int* in_sizes, int n_in,
                              void* d_out, int out_size)
{
    (void)in_sizes; (void)n_in;
    const float* X  = (const float*)d_in[0];
    const float* A  = (const float*)d_in[1];
    const float* Wg[3]  = {(const float*)d_in[2], (const float*)d_in[6],  (const float*)d_in[10]};
    const float* ag[3]  = {(const float*)d_in[3], (const float*)d_in[7],  (const float*)d_in[11]};
    const float* Ws[3]  = {(const float*)d_in[4], (const float*)d_in[8],  (const float*)d_in[12]};
    const float* as_[3] = {(const float*)d_in[5], (const float*)d_in[9],  (const float*)d_in[13]};
    const float* Wd = (const float*)d_in[14];
    const float* bd = (const float*)d_in[15];
    float* out = (float*)d_out;

    float *whz, *whs, *z, *s, *att, *t, *gg;
    float *xp, *ap, *xq, *aq, *x3, *a3;
    float *f1z, *f2z, *f1s, *f2s;
    cudaGetSymbolAddress((void**)&whz, g_Whz);
    cudaGetSymbolAddress((void**)&whs, g_Whs);
    cudaGetSymbolAddress((void**)&z,   g_Zb);
    cudaGetSymbolAddress((void**)&s,   g_Sb);
    cudaGetSymbolAddress((void**)&att, g_att);
    cudaGetSymbolAddress((void**)&t,   g_Tb);
    cudaGetSymbolAddress((void**)&gg,  g_Gb);
    cudaGetSymbolAddress((void**)&xp,  g_Xp);
    cudaGetSymbolAddress((void**)&ap,  g_Ap);
    cudaGetSymbolAddress((void**)&xq,  g_Xq);
    cudaGetSymbolAddress((void**)&aq,  g_Aq);
    cudaGetSymbolAddress((void**)&x3,  g_X3);
    cudaGetSymbolAddress((void**)&a3,  g_A3);
    cudaGetSymbolAddress((void**)&f1z, g_f1z);
    cudaGetSymbolAddress((void**)&f2z, g_f2z);
    cudaGetSymbolAddress((void**)&f1s, g_f1s);
    cudaGetSymbolAddress((void**)&f2s, g_f2s);

    k_zero_losses<<<1, 1>>>();

    // layer 0: N=1024, Fin=128, Fz=256, c=64
    run_layer(X, A, Wg[0], ag[0], Ws[0], as_[0], xp, ap,
              1024, 128, 256, 64, whz, whs, z, s, att, t, gg, f1z, f2z, f1s, f2s);
    // layer 1: N=64, Fin=256, Fz=256, c=8
    run_layer(xp, ap, Wg[1], ag[1], Ws[1], as_[1], xq, aq,
              64, 256, 256, 8, whz, whs, z, s, att, t, gg, f1z, f2z, f1s, f2s);
    // layer 2: N=8, Fin=256, Fz=256, c=1
    run_layer(xq, aq, Wg[2], ag[2], Ws[2], as_[2], x3, a3,
              8, 256, 256, 1, whz, whs, z, s, att, t, gg, f1z, f2z, f1s, f2s);

    final_logits<<<1, 192>>>(x3, Wd, bd, out, out_size);
    write_tail<<<1, 32>>>(a3, out, out_size);
}

// round 3
// speedup vs baseline: 1.0135x; 1.0135x over previous
#include <cuda_runtime.h>
#include <math.h>

#define BATCH 16
#define NCLASS 10

// ---------------- scratch (static __device__, allocation-free) ----------------
__device__ float g_Whz[(size_t)BATCH * 1024 * 256];   // 16 MB
__device__ float g_Whs[(size_t)BATCH * 1024 * 64];    // 4 MB
__device__ float g_Zb [(size_t)BATCH * 1024 * 256];   // 16 MB
__device__ float g_Sb [(size_t)BATCH * 1024 * 64];    // 4 MB
__device__ float g_Tb [(size_t)BATCH * 64 * 1024];    // 4 MB
__device__ float g_Gb [(size_t)BATCH * 64 * 64];
__device__ float g_Xp [(size_t)BATCH * 64 * 256];
__device__ float g_Ap [(size_t)BATCH * 64 * 64];
__device__ float g_Xq [(size_t)BATCH * 8 * 256];
__device__ float g_Aq [(size_t)BATCH * 8 * 8];
__device__ float g_X3 [(size_t)BATCH * 256];
__device__ float g_A3 [(size_t)BATCH];
__device__ float g_f1z[BATCH * 1024];
__device__ float g_f2z[BATCH * 1024];
__device__ float g_f1s[BATCH * 1024];
__device__ float g_f2s[BATCH * 1024];
__device__ float g_mz [BATCH * 1024];
__device__ float g_iz [BATCH * 1024];
__device__ float g_ms [BATCH * 1024];
__device__ float g_is [BATCH * 1024];
__device__ double g_link, g_ent, g_tot;

// ---------------- generic tiled GEMM ----------------
template<int BM, int BN, int BK, int TM, int TN, bool TA, bool RELU>
__global__ __launch_bounds__((BM / TM) * (BN / TN))
void gemm_k(const float* __restrict__ Ag, const float* __restrict__ Bg,
            float* __restrict__ Cg, int M, int N, int K,
            long sA, long sB, long sC)
{
    constexpr int THREADS = (BM / TM) * (BN / TN);
    const float* Ab = Ag + (long)blockIdx.z * sA;
    const float* Bb = Bg + (long)blockIdx.z * sB;
    float* Cb = Cg + (long)blockIdx.z * sC;
    __shared__ float As[BK][BM + 4];
    __shared__ float Bs[BK][BN + 4];
    const int bm = blockIdx.y * BM, bn = blockIdx.x * BN;
    const int tid = threadIdx.x;
    constexpr int TCOLS = BN / TN;
    const int tx = tid % TCOLS, ty = tid / TCOLS;
    float acc[TM][TN];
#pragma unroll
    for (int i = 0; i < TM; i++)
#pragma unroll
        for (int j = 0; j < TN; j++) acc[i][j] = 0.f;

    for (int k0 = 0; k0 < K; k0 += BK) {
        if (!TA) {
            for (int idx = tid; idx < BM * BK; idx += THREADS) {
                int kk = idx % BK, m = idx / BK;
                int gm = bm + m, gk = k0 + kk;
                As[kk][m] = (gm < M && gk < K) ? Ab[(long)gm * K + gk] : 0.f;
            }
        } else {
            for (int idx = tid; idx < BM * BK; idx += THREADS) {
                int m = idx % BM, kk = idx / BM;
                int gm = bm + m, gk = k0 + kk;
                As[kk][m] = (gm < M && gk < K) ? Ab[(long)gk * M + gm] : 0.f;
            }
        }
        for (int idx = tid; idx < BK * BN; idx += THREADS) {
            int n = idx % BN, kk = idx / BN;
            int gn = bn + n, gk = k0 + kk;
            Bs[kk][n] = (gn < N && gk < K) ? Bb[(long)gk * N + gn] : 0.f;
        }
        __syncthreads();
#pragma unroll
        for (int kk = 0; kk < BK; kk++) {
            float ra[TM], rb[TN];
#pragma unroll
            for (int i = 0; i < TM; i++) ra[i] = As[kk][ty * TM + i];
#pragma unroll
            for (int j = 0; j < TN; j++) rb[j] = Bs[kk][tx * TN + j];
#pragma unroll
            for (int i = 0; i < TM; i++)
#pragma unroll
                for (int j = 0; j < TN; j++) acc[i][j] += ra[i] * rb[j];
        }
        __syncthreads();
    }
#pragma unroll
    for (int i = 0; i < TM; i++) {
        int gm = bm + ty * TM + i;
        if (gm >= M) continue;
#pragma unroll
        for (int j = 0; j < TN; j++) {
            int gn = bn + tx * TN + j;
            if (gn >= N) continue;
            float v = acc[i][j];
            if (RELU) v = v > 0.f ? v : 0.f;
            Cb[(long)gm * N + gn] = v;
        }
    }
}

// ---------------- fused attention-aggregation GEMM ----------------
// C[b,i,n] = relu?( sum_j P[b,i,j] * Wh[b,j,n] )
// P[i,j] = expf( (A[i,j]>0 ? lrelu(f1_i+f2_j) : -9e15) - m_i ) * inv_i
// Masked entries underflow to exactly 0 since m_i is finite (self-loops).
template<int BM, int BN, int BK, int TM, int TN, bool RELU>
__global__ __launch_bounds__((BM / TM) * (BN / TN))
void agg_k(const float* __restrict__ A, const float* __restrict__ Wh,
           const float* __restrict__ f1, const float* __restrict__ f2,
           const float* __restrict__ rm, const float* __restrict__ ri,
           float* __restrict__ C, int N, int F)
{
    constexpr int THREADS = (BM / TM) * (BN / TN);
    const int b = blockIdx.z;
    const float* Ab  = A  + (size_t)b * N * N;
    const float* Whb = Wh + (size_t)b * N * F;
    float* Cb = C + (size_t)b * N * F;
    const float* f1b = f1 + (size_t)b * N;
    const float* f2b = f2 + (size_t)b * N;
    const float* rmb = rm + (size_t)b * N;
    const float* rib = ri + (size_t)b * N;

    __shared__ float Ps[BK][BM + 4];
    __shared__ float Bs[BK][BN + 4];
    __shared__ float s_f1[BM], s_m[BM], s_i[BM];

    const int bm = blockIdx.y * BM, bn = blockIdx.x * BN;
    const int tid = threadIdx.x;
    constexpr int TCOLS = BN / TN;
    const int tx = tid % TCOLS, ty = tid / TCOLS;

    for (int i = tid; i < BM; i += THREADS) {
        int gi = bm + i;
        if (gi < N) { s_f1[i] = f1b[gi]; s_m[i] = rmb[gi]; s_i[i] = rib[gi]; }
        else        { s_f1[i] = 0.f; s_m[i] = 0.f; s_i[i] = 0.f; }
    }
    __syncthreads();

    float acc[TM][TN];
#pragma unroll
    for (int i = 0; i < TM; i++)
#pragma unroll
        for (int j = 0; j < TN; j++) acc[i][j] = 0.f;

    for (int k0 = 0; k0 < N; k0 += BK) {
        // on-the-fly P tile
        for (int idx = tid; idx < BM * BK; idx += THREADS) {
            int jj = idx % BK, ii = idx / BK;
            int gi = bm + ii, gj = k0 + jj;
            float p = 0.f;
            if (gi < N && gj < N) {
                float a = Ab[(size_t)gi * N + gj];
                float x = s_f1[ii] + f2b[gj];
                float e = (x > 0.f) ? x : 0.2f * x;
                if (!(a > 0.f)) e = -9e15f;
                p = __expf(e - s_m[ii]) * s_i[ii];
            }
            Ps[jj][ii] = p;
        }
        // Wh tile
        for (int idx = tid; idx < BK * BN; idx += THREADS) {
            int n = idx % BN, kk = idx / BN;
            int gn = bn + n, gk = k0 + kk;
            Bs[kk][n] = (gn < F && gk < N) ? Whb[(size_t)gk * F + gn] : 0.f;
        }
        __syncthreads();
#pragma unroll
        for (int kk = 0; kk < BK; kk++) {
            float ra[TM], rb[TN];
#pragma unroll
            for (int i = 0; i < TM; i++) ra[i] = Ps[kk][ty * TM + i];
#pragma unroll
            for (int j = 0; j < TN; j++) rb[j] = Bs[kk][tx * TN + j];
#pragma unroll
            for (int i = 0; i < TM; i++)
#pragma unroll
                for (int j = 0; j < TN; j++) acc[i][j] += ra[i] * rb[j];
        }
        __syncthreads();
    }
#pragma unroll
    for (int i = 0; i < TM; i++) {
        int gm = bm + ty * TM + i;
        if (gm >= N) continue;
#pragma unroll
        for (int j = 0; j < TN; j++) {
            int gn = bn + tx * TN + j;
            if (gn >= F) continue;
            float v = acc[i][j];
            if (RELU) v = v > 0.f ? v : 0.f;
            Cb[(size_t)gm * F + gn] = v;
        }
    }
}

// ---------------- row stats: max + 1/sumexp for BOTH attentions + sum(A^2) ----------------
__global__ void rowstat_k(const float* __restrict__ A,
                          const float* __restrict__ f1z, const float* __restrict__ f2z,
                          const float* __restrict__ f1s, const float* __restrict__ f2s,
                          float* __restrict__ mz, float* __restrict__ iz,
                          float* __restrict__ ms, float* __restrict__ is_, int N)
{
    int row = blockIdx.x;          // b*N + i
    int b = row / N;
    const float* Ar = A + (size_t)row * N;
    const float* f2zb = f2z + (size_t)b * N;
    const float* f2sb = f2s + (size_t)b * N;
    float fz = f1z[row], fs = f1s[row];
    int t = threadIdx.x;
    float ez[4], es[4];
    float mzl = -1e30f, msl = -1e30f;
    double ss = 0.0;
#pragma unroll
    for (int it = 0; it < 4; it++) {
        int j = t + it * 256;
        float vz = -9e15f, vs = -9e15f;
        if (j < N) {
            float a = Ar[j];
            ss += (double)a * (double)a;
            bool on = a > 0.f;
            float xz = fz + f2zb[j];
            float xs = fs + f2sb[j];
            float lz = (xz > 0.f) ? xz : 0.2f * xz;
            float ls = (xs > 0.f) ? xs : 0.2f * xs;
            vz = on ? lz : -9e15f;
            vs = on ? ls : -9e15f;
        }
        ez[it] = vz; es[it] = vs;
        mzl = fmaxf(mzl, vz); msl = fmaxf(msl, vs);
    }
    __shared__ float sh[256];
    sh[t] = mzl; __syncthreads();
    for (int s = 128; s > 0; s >>= 1) { if (t < s) sh[t] = fmaxf(sh[t], sh[t + s]); __syncthreads(); }
    float Mz = sh[0]; __syncthreads();
    sh[t] = msl; __syncthreads();
    for (int s = 128; s > 0; s >>= 1) { if (t < s) sh[t] = fmaxf(sh[t], sh[t + s]); __syncthreads(); }
    float Ms = sh[0]; __syncthreads();

    float sz = 0.f, ssum = 0.f;
#pragma unroll
    for (int it = 0; it < 4; it++) {
        int j = t + it * 256;
        if (j < N) { sz += __expf(ez[it] - Mz); ssum += __expf(es[it] - Ms); }
    }
    sh[t] = sz; __syncthreads();
    for (int s = 128; s > 0; s >>= 1) { if (t < s) sh[t] += sh[t + s]; __syncthreads(); }
    float Sz = sh[0]; __syncthreads();
    sh[t] = ssum; __syncthreads();
    for (int s = 128; s > 0; s >>= 1) { if (t < s) sh[t] += sh[t + s]; __syncthreads(); }
    float Ss = sh[0]; __syncthreads();

    // sum(A^2) reduction (double)
    __shared__ double dh[256];
    dh[t] = ss; __syncthreads();
    for (int s = 128; s > 0; s >>= 1) { if (t < s) dh[t] += dh[t + s]; __syncthreads(); }

    if (t == 0) {
        mz[row] = Mz; iz[row] = 1.f / Sz;
        ms[row] = Ms; is_[row] = 1.f / Ss;
        atomicAdd(&g_tot, dh[0]);
    }
}

// ---------------- f1/f2 = Wh . a[:F], Wh . a[F:] (warp per row) ----------------
__global__ void fvec_k(const float* __restrict__ Wh, const float* __restrict__ a,
                       float* __restrict__ f1, float* __restrict__ f2,
                       int rows, int F)
{
    int w = (blockIdx.x * blockDim.x + threadIdx.x) >> 5;
    int lane = threadIdx.x & 31;
    if (w >= rows) return;
    const float* p = Wh + (size_t)w * F;
    float s1 = 0.f, s2 = 0.f;
    for (int f = lane; f < F; f += 32) {
        float v = p[f];
        s1 += v * a[f];
        s2 += v * a[F + f];
    }
#pragma unroll
    for (int o = 16; o > 0; o >>= 1) {
        s1 += __shfl_down_sync(0xffffffffu, s1, o);
        s2 += __shfl_down_sync(0xffffffffu, s2, o);
    }
    if (lane == 0) { f1[w] = s1; f2[w] = s2; }
}

// ---------------- softmax over c (warp per row) + entropy accumulation ----------------
__global__ void softmax_c_ent(float* __restrict__ S, int rows, int c, double inv_rows)
{
    int w = (blockIdx.x * blockDim.x + threadIdx.x) >> 5;
    int lane = threadIdx.x & 31;
    if (w >= rows) return;
    float* p = S + (size_t)w * c;
    float v[2] = {-1e30f, -1e30f};
    float m = -1e30f;
#pragma unroll
    for (int i = 0; i < 2; i++) {
        int f = lane + 32 * i;
        if (f < c) { v[i] = p[f]; m = fmaxf(m, v[i]); }
    }
#pragma unroll
    for (int o = 16; o > 0; o >>= 1) m = fmaxf(m, __shfl_xor_sync(0xffffffffu, m, o));
    float s = 0.f;
#pragma unroll
    for (int i = 0; i < 2; i++) {
        int f = lane + 32 * i;
        if (f < c) { v[i] = __expf(v[i] - m); s += v[i]; }
    }
#pragma unroll
    for (int o = 16; o > 0; o >>= 1) s += __shfl_xor_sync(0xffffffffu, s, o);
    float inv = 1.f / s;
    double erow = 0.0;
#pragma unroll
    for (int i = 0; i < 2; i++) {
        int f = lane + 32 * i;
        if (f < c) {
            float q = v[i] * inv;
            p[f] = q;
            erow += -(double)q * (double)logf(q + 1e-15f);
        }
    }
#pragma unroll
    for (int o = 16; o > 0; o >>= 1) erow += __shfl_down_sync(0xffffffffu, erow, o);
    if (lane == 0) atomicAdd(&g_ent, erow * inv_rows);
}

// ---------------- loss reductions ----------------
__global__ void accum_sq(const float* __restrict__ x, long n)
{
    __shared__ double sh[256];
    long i = (long)blockIdx.x * blockDim.x + threadIdx.x;
    double s = 0.0;
    long stride = (long)gridDim.x * blockDim.x;
    for (; i < n; i += stride) { double v = x[i]; s += v * v; }
    sh[threadIdx.x] = s; __syncthreads();
    for (int r = 128; r > 0; r >>= 1) { if (threadIdx.x < r) sh[threadIdx.x] += sh[threadIdx.x + r]; __syncthreads(); }
    if (threadIdx.x == 0) atomicAdd(&g_tot, sh[0]);
}

__global__ void trace_neg2(const float* __restrict__ Anew, int total, int c)
{
    int t = blockIdx.x * blockDim.x + threadIdx.x;
    if (t >= total) return;
    int b = t / c, j = t % c;
    atomicAdd(&g_tot, -2.0 * (double)Anew[((long)b * c + j) * c + j]);
}

__global__ void k_zero_losses() { g_link = 0.0; g_ent = 0.0; g_tot = 0.0; }
__global__ void k_zero_tot()    { g_tot = 0.0; }
__global__ void k_finalize_link(double denom)
{
    double v = g_tot;
    g_link += sqrt(v > 0.0 ? v : 0.0) / denom;
}

// ---------------- final dense + output assembly ----------------
__global__ void final_logits(const float* __restrict__ X3, const float* __restrict__ Wd,
                             const float* __restrict__ bd, float* __restrict__ out, int out_size)
{
    int t = blockIdx.x * blockDim.x + threadIdx.x;
    if (t >= BATCH * NCLASS) return;
    int b = t / NCLASS, cls = t % NCLASS;
    float s = bd[cls];
    const float* xr = X3 + (long)b * 256;
    for (int f = 0; f < 256; f++) s += xr[f] * Wd[f * NCLASS + cls];
    if (t < out_size) out[t] = s;
}

__global__ void write_tail(const float* __restrict__ A3, float* __restrict__ out, int out_size)
{
    int t = threadIdx.x;
    if (t < BATCH && 160 + t < out_size) out[160 + t] = A3[t];
    if (t == 0) {
        if (176 < out_size) out[176] = (float)g_link;
        if (177 < out_size) out[177] = (float)g_ent;
    }
}

// ---------------- host-side dispatch helpers ----------------
static void gemm_nn_big(const float* A, const float* B, float* C, int M, int N, int K,
                        long sA, long sB, long sC, bool relu)
{
    dim3 g((N + 127) / 128, (M + 127) / 128, BATCH);
    if (relu) gemm_k<128, 128, 16, 8, 8, false, true ><<<g, 256>>>(A, B, C, M, N, K, sA, sB, sC);
    else      gemm_k<128, 128, 16, 8, 8, false, false><<<g, 256>>>(A, B, C, M, N, K, sA, sB, sC);
}
static void gemm_nn_n64(const float* A, const float* B, float* C, int M, int N, int K,
                        long sA, long sB, long sC, bool relu)
{
    dim3 g((N + 63) / 64, (M + 127) / 128, BATCH);
    if (relu) gemm_k<128, 64, 16, 8, 4, false, true ><<<g, 256>>>(A, B, C, M, N, K, sA, sB, sC);
    else      gemm_k<128, 64, 16, 8, 4, false, false><<<g, 256>>>(A, B, C, M, N, K, sA, sB, sC);
}
static void gemm_tn_m64(const float* A, const float* B, float* C, int M, int N, int K,
                        long sA, long sB, long sC)
{
    dim3 g((N + 127) / 128, (M + 63) / 64, BATCH);
    gemm_k<64, 128, 16, 4, 8, true, false><<<g, 256>>>(A, B, C, M, N, K, sA, sB, sC);
}
static void gemm_nn_64(const float* A, const float* B, float* C, int M, int N, int K,
                       long sA, long sB, long sC)
{
    dim3 g((N + 63) / 64, (M + 63) / 64, BATCH);
    gemm_k<64, 64, 16, 4, 4, false, false><<<g, 256>>>(A, B, C, M, N, K, sA, sB, sC);
}
static void gemm_tn_64(const float* A, const float* B, float* C, int M, int N, int K,
                       long sA, long sB, long sC)
{
    dim3 g((N + 63) / 64, (M + 63) / 64, BATCH);
    gemm_k<64, 64, 16, 4, 4, true, false><<<g, 256>>>(A, B, C, M, N, K, sA, sB, sC);
}

static int grid_for(long n) { long b = (n + 255) / 256; return (int)(b < 2048 ? b : 2048); }

// One GAT+pool layer.
static void run_layer(const float* X, const float* A,
                      const float* Wg, const float* ag, const float* Ws, const float* as_,
                      float* Xout, float* Aout,
                      int N, int Fin, int Fz, int c,
                      float* whz, float* whs, float* z, float* s, float* t, float* gg,
                      float* f1z, float* f2z, float* f1s, float* f2s,
                      float* mz, float* iz, float* ms, float* is_)
{
    int rows = BATCH * N;
    long sX = (long)N * Fin;

    gemm_nn_big(X, Wg, whz, N, Fz, Fin, sX, 0, (long)N * Fz, false);
    gemm_nn_n64(X, Ws, whs, N, c, Fin, sX, 0, (long)N * c, false);

    int fblocks = (rows * 32 + 255) / 256;
    fvec_k<<<fblocks, 256>>>(whz, ag, f1z, f2z, rows, Fz);
    fvec_k<<<fblocks, 256>>>(whs, as_, f1s, f2s, rows, c);

    // stats pass: one read of A, both attentions + sum(A^2)
    k_zero_tot<<<1, 1>>>();
    rowstat_k<<<rows, 256>>>(A, f1z, f2z, f1s, f2s, mz, iz, ms, is_, N);

    // Z = relu(P_z @ Wh_z): fused, att never materialized
    {
        dim3 g((Fz + 255) / 256, (N + 63) / 64, BATCH);
        agg_k<64, 256, 32, 8, 8, true><<<g, 256>>>(A, whz, f1z, f2z, mz, iz, z, N, Fz);
    }
    // S_pre = relu(P_s @ Wh_s): fused
    {
        dim3 g((c + 63) / 64, (N + 63) / 64, BATCH);
        agg_k<64, 64, 32, 4, 4, true><<<g, 256>>>(A, whs, f1s, f2s, ms, is_, s, N, c);
    }
    softmax_c_ent<<<(rows + 7) / 8, 256>>>(s, rows, c, 1.0 / (double)rows);

    // T = S^T A ;  A_new = T S ;  X_new = S^T Z ;  G = S^T S
    gemm_tn_m64(s, A, t, c, N, N, (long)N * c, (long)N * N, (long)c * N);
    gemm_nn_64(t, s, Aout, c, c, N, (long)c * N, (long)N * c, (long)c * c);
    gemm_tn_m64(s, z, Xout, c, Fz, N, (long)N * c, (long)N * Fz, (long)c * Fz);
    gemm_tn_64(s, s, gg, c, c, N, (long)N * c, (long)N * c, (long)c * c);

    // link loss: ||A - S S^T||_F^2 = sum(A^2) - 2 tr(S^T A S) + ||S^T S||_F^2
    trace_neg2<<<(BATCH * c + 255) / 256, 256>>>(Aout, BATCH * c, c);
    long nG = (long)BATCH * c * c;
    accum_sq<<<grid_for(nG), 256>>>(gg, nG);
    long nA = (long)BATCH * N * N;
    k_finalize_link<<<1, 1>>>((double)nA);
}

extern "C" void kernel_launch(void* const* d_in, const int* in_sizes, int n_in,
                              void* d_out, int out_size)
{
    (void)in_sizes; (void)n_in;
    const float* X  = (const float*)d_in[0];
    const float* A  = (const float*)d_in[1];
    const float* Wg[3]  = {(const float*)d_in[2], (const float*)d_in[6],  (const float*)d_in[10]};
    const float* ag[3]  = {(const float*)d_in[3], (const float*)d_in[7],  (const float*)d_in[11]};
    const float* Ws[3]  = {(const float*)d_in[4], (const float*)d_in[8],  (const float*)d_in[12]};
    const float* as_[3] = {(const float*)d_in[5], (const float*)d_in[9],  (const float*)d_in[13]};
    const float* Wd = (const float*)d_in[14];
    const float* bd = (const float*)d_in[15];
    float* out = (float*)d_out;

    float *whz, *whs, *z, *s, *t, *gg;
    float *xp, *ap, *xq, *aq, *x3, *a3;
    float *f1z, *f2z, *f1s, *f2s, *mz, *iz, *ms, *is_;
    cudaGetSymbolAddress((void**)&whz, g_Whz);
    cudaGetSymbolAddress((void**)&whs, g_Whs);
    cudaGetSymbolAddress((void**)&z,   g_Zb);
    cudaGetSymbolAddress((void**)&s,   g_Sb);
    cudaGetSymbolAddress((void**)&t,   g_Tb);
    cudaGetSymbolAddress((void**)&gg,  g_Gb);
    cudaGetSymbolAddress((void**)&xp,  g_Xp);
    cudaGetSymbolAddress((void**)&ap,  g_Ap);
    cudaGetSymbolAddress((void**)&xq,  g_Xq);
    cudaGetSymbolAddress((void**)&aq,  g_Aq);
    cudaGetSymbolAddress((void**)&x3,  g_X3);
    cudaGetSymbolAddress((void**)&a3,  g_A3);
    cudaGetSymbolAddress((void**)&f1z, g_f1z);
    cudaGetSymbolAddress((void**)&f2z, g_f2z);
    cudaGetSymbolAddress((void**)&f1s, g_f1s);
    cudaGetSymbolAddress((void**)&f2s, g_f2s);
    cudaGetSymbolAddress((void**)&mz,  g_mz);
    cudaGetSymbolAddress((void**)&iz,  g_iz);
    cudaGetSymbolAddress((void**)&ms,  g_ms);
    cudaGetSymbolAddress((void**)&is_, g_is);

    k_zero_losses<<<1, 1>>>();

    // layer 0: N=1024, Fin=128, Fz=256, c=64
    run_layer(X, A, Wg[0], ag[0], Ws[0], as_[0], xp, ap,
              1024, 128, 256, 64, whz, whs, z, s, t, gg,
              f1z, f2z, f1s, f2s, mz, iz, ms, is_);
    // layer 1: N=64, Fin=256, Fz=256, c=8
    run_layer(xp, ap, Wg[1], ag[1], Ws[1], as_[1], xq, aq,
              64, 256, 256, 8, whz, whs, z, s, t, gg,
              f1z, f2z, f1s, f2s, mz, iz, ms, is_);
    // layer 2: N=8, Fin=256, Fz=256, c=1
    run_layer(xq, aq, Wg[2], ag[2], Ws[2], as_[2], x3, a3,
              8, 256, 256, 1, whz, whs, z, s, t, gg,
              f1z, f2z, f1s, f2s, mz, iz, ms, is_);

    final_logits<<<1, 192>>>(x3, Wd, bd, out, out_size);
    write_tail<<<1, 32>>>(a3, out, out_size);
}

// round 5
// speedup vs baseline: 1.8087x; 1.7846x over previous
#include <cuda_runtime.h>
#include <math.h>
#include <stdint.h>

#define BATCH 16
#define NCLASS 10

// ---------------- scratch (static __device__, allocation-free) ----------------
__device__ float g_Whz[(size_t)BATCH * 1024 * 256];
__device__ float g_Whs[(size_t)BATCH * 1024 * 64];
__device__ float g_Zb [(size_t)BATCH * 1024 * 256];
__device__ float g_Sb [(size_t)BATCH * 1024 * 64];
__device__ float g_Tb [(size_t)BATCH * 64 * 1024];
__device__ float g_Gb [(size_t)BATCH * 64 * 64];
__device__ float g_Xp [(size_t)BATCH * 64 * 256];
__device__ float g_Ap [(size_t)BATCH * 64 * 64];
__device__ float g_Xq [(size_t)BATCH * 8 * 256];
__device__ float g_Aq [(size_t)BATCH * 8 * 8];
__device__ float g_X3 [(size_t)BATCH * 256];
__device__ float g_A3 [(size_t)BATCH];
__device__ float g_f1z[BATCH * 1024];
__device__ float g_f2z[BATCH * 1024];
__device__ float g_f1s[BATCH * 1024];
__device__ float g_f2s[BATCH * 1024];
__device__ float g_mz [BATCH * 1024];
__device__ float g_iz [BATCH * 1024];
__device__ float g_ms [BATCH * 1024];
__device__ float g_is [BATCH * 1024];
__device__ double g_link, g_ent, g_tot;

__device__ __forceinline__ uint32_t to_tf32(float x) {
    uint32_t r; asm("cvt.rna.tf32.f32 %0, %1;" : "=r"(r) : "f"(x)); return r;
}
// 3xTF32 split: x ~= hi + lo, both tf32-representable.
__device__ __forceinline__ void split_tf32(float x, uint32_t& hi, uint32_t& lo) {
    hi = to_tf32(x);
    lo = to_tf32(x - __uint_as_float(hi));
}

#define AM_NN    0
#define AM_TN    1
#define AM_FUSED 2

// ---------------- 3xTF32 warp-MMA GEMM (fp32-accurate) ----------------
// C[b] = op(A[b]) * B[b] via mma.sync.m16n8k8.tf32 with hi/lo split:
//   C += Ahi*Bhi + Ahi*Blo + Alo*Bhi
// AM_NN: A is MxK row-major. AM_TN: A stored KxM (compute A^T B).
// AM_FUSED: attention P generated on the fly from adjacency + f1/f2/rm/ri.
// B is KxN row-major. 8 warps: 2 (m) x 4 (n).
template<int BM, int BN, int AM, bool RELU>
__global__ __launch_bounds__(256)
void mma_k(const float* __restrict__ Ag, const float* __restrict__ Bg,
           float* __restrict__ Cg, int M, int N, int K,
           long sA, long sB, long sC,
           const float* __restrict__ f1, const float* __restrict__ f2,
           const float* __restrict__ rm, const float* __restrict__ ri)
{
    constexpr int BK  = 16;
    constexpr int PAD = 8;
    constexpr int WM  = BM / 2;
    constexpr int WN  = BN / 4;
    constexpr int MT  = WM / 16;
    constexpr int NT  = WN / 8;
    constexpr int ALD = (BM * BK) / 256;
    constexpr int BLD = (BN * BK) / 256;

    __shared__ uint32_t AsH[BK][BM + PAD];
    __shared__ uint32_t AsL[BK][BM + PAD];
    __shared__ uint32_t BsH[BK][BN + PAD];
    __shared__ uint32_t BsL[BK][BN + PAD];
    __shared__ float s_f1[BM], s_m[BM], s_i[BM];

    const int b = blockIdx.z;
    const float* Ab = Ag + (long)b * sA;
    const float* Bb = Bg + (long)b * sB;
    float* Cb = Cg + (long)b * sC;

    const int bm = blockIdx.y * BM, bn = blockIdx.x * BN;
    const int tid  = threadIdx.x;
    const int warp = tid >> 5, lane = tid & 31;
    const int wm = (warp >> 2) * WM, wn = (warp & 3) * WN;
    const int lg = lane >> 2, lt = lane & 3;

    const float* f2b = nullptr;
    if (AM == AM_FUSED) {
        f2b = f2 + (long)b * K;
        const float* f1b = f1 + (long)b * K;
        const float* rmb = rm + (long)b * K;
        const float* rib = ri + (long)b * K;
        for (int i = tid; i < BM; i += 256) {
            int gi = bm + i;
            if (gi < M) { s_f1[i] = f1b[gi]; s_m[i] = rmb[gi]; s_i[i] = rib[gi]; }
            else        { s_f1[i] = 0.f; s_m[i] = 0.f; s_i[i] = 0.f; }
        }
    }

    float acc[MT][NT][4];
#pragma unroll
    for (int mt = 0; mt < MT; mt++)
#pragma unroll
        for (int nt = 0; nt < NT; nt++)
#pragma unroll
            for (int q = 0; q < 4; q++) acc[mt][nt][q] = 0.f;

    float rA[ALD], rB[BLD];
    float rF[(AM == AM_FUSED) ? ALD : 1];

    auto loadA = [&](int k0) {
#pragma unroll
        for (int t = 0; t < ALD; t++) {
            int idx = tid + 256 * t;
            if (AM == AM_NN) {
                int kk = idx & (BK - 1), m = idx >> 4;
                int gm = bm + m, gk = k0 + kk;
                rA[t] = (gm < M && gk < K) ? Ab[(long)gm * K + gk] : 0.f;
            } else if (AM == AM_TN) {
                int m = idx % BM, kk = idx / BM;
                int gm = bm + m, gk = k0 + kk;
                rA[t] = (gm < M && gk < K) ? Ab[(long)gk * M + gm] : 0.f;
            } else {
                int jj = idx & (BK - 1), ii = idx >> 4;
                int gi = bm + ii, gj = k0 + jj;
                bool ok = (gi < M && gj < K);
                rA[t] = ok ? Ab[(long)gi * K + gj] : 0.f;
                rF[t] = ok ? f2b[gj] : 0.f;
            }
        }
    };
    auto loadB = [&](int k0) {
#pragma unroll
        for (int t = 0; t < BLD; t++) {
            int idx = tid + 256 * t;
            int n = idx % BN, kk = idx / BN;
            int gn = bn + n, gk = k0 + kk;
            rB[t] = (gn < N && gk < K) ? Bb[(long)gk * N + gn] : 0.f;
        }
    };
    auto storeAB = [&]() {
#pragma unroll
        for (int t = 0; t < ALD; t++) {
            int idx = tid + 256 * t;
            float v; int r0, c0;
            if (AM == AM_NN) {
                c0 = idx & (BK - 1); r0 = idx >> 4; v = rA[t];
            } else if (AM == AM_TN) {
                r0 = idx % BM; c0 = idx / BM; v = rA[t];
            } else {
                c0 = idx & (BK - 1); r0 = idx >> 4;
                float x = s_f1[r0] + rF[t];
                float e = (x > 0.f) ? x : 0.2f * x;
                if (!(rA[t] > 0.f)) e = -9e15f;
                v = __expf(e - s_m[r0]) * s_i[r0];
            }
            uint32_t hi, lo; split_tf32(v, hi, lo);
            AsH[c0][r0] = hi; AsL[c0][r0] = lo;
        }
#pragma unroll
        for (int t = 0; t < BLD; t++) {
            int idx = tid + 256 * t;
            int n = idx % BN, kk = idx / BN;
            uint32_t hi, lo; split_tf32(rB[t], hi, lo);
            BsH[kk][n] = hi; BsL[kk][n] = lo;
        }
    };

    loadA(0); loadB(0);
    __syncthreads();                      // covers s_f1/s_m/s_i init too

    for (int k0 = 0; k0 < K; k0 += BK) {
        storeAB();
        __syncthreads();
        if (k0 + BK < K) { loadA(k0 + BK); loadB(k0 + BK); }   // prefetch under compute

#pragma unroll
        for (int ks = 0; ks < BK; ks += 8) {
            uint32_t ah[MT][4], al[MT][4], bh[NT][2], bl[NT][2];
#pragma unroll
            for (int mt = 0; mt < MT; mt++) {
                int r = wm + mt * 16;
                ah[mt][0] = AsH[ks + lt    ][r + lg];
                ah[mt][1] = AsH[ks + lt    ][r + lg + 8];
                ah[mt][2] = AsH[ks + lt + 4][r + lg];
                ah[mt][3] = AsH[ks + lt + 4][r + lg + 8];
                al[mt][0] = AsL[ks + lt    ][r + lg];
                al[mt][1] = AsL[ks + lt    ][r + lg + 8];
                al[mt][2] = AsL[ks + lt + 4][r + lg];
                al[mt][3] = AsL[ks + lt + 4][r + lg + 8];
            }
#pragma unroll
            for (int nt = 0; nt < NT; nt++) {
                int cidx = wn + nt * 8 + lg;
                bh[nt][0] = BsH[ks + lt    ][cidx];
                bh[nt][1] = BsH[ks + lt + 4][cidx];
                bl[nt][0] = BsL[ks + lt    ][cidx];
                bl[nt][1] = BsL[ks + lt + 4][cidx];
            }
#define MMA_STEP(AF, BF)                                                        \
            asm volatile(                                                       \
                "mma.sync.aligned.m16n8k8.row.col.f32.tf32.tf32.f32 "           \
                "{%0,%1,%2,%3}, {%4,%5,%6,%7}, {%8,%9}, {%0,%1,%2,%3};"         \
                : "+f"(acc[mt][nt][0]), "+f"(acc[mt][nt][1]),                   \
                  "+f"(acc[mt][nt][2]), "+f"(acc[mt][nt][3])                    \
                : "r"(AF[mt][0]), "r"(AF[mt][1]), "r"(AF[mt][2]), "r"(AF[mt][3]),\
                  "r"(BF[nt][0]), "r"(BF[nt][1]))
#pragma unroll
            for (int mt = 0; mt < MT; mt++)
#pragma unroll
                for (int nt = 0; nt < NT; nt++) {
                    MMA_STEP(ah, bl);   // cross terms first (small)
                    MMA_STEP(al, bh);
                    MMA_STEP(ah, bh);   // main term
                }
#undef MMA_STEP
        }
        __syncthreads();
    }

    // epilogue: c0:(g,2lt) c1:(g,2lt+1) c2:(g+8,2lt) c3:(g+8,2lt+1)
#pragma unroll
    for (int mt = 0; mt < MT; mt++) {
#pragma unroll
        for (int nt = 0; nt < NT; nt++) {
            int gm = bm + wm + mt * 16 + lg;
            int gn = bn + wn + nt * 8 + 2 * lt;
            float v0 = acc[mt][nt][0], v1 = acc[mt][nt][1];
            float v2 = acc[mt][nt][2], v3 = acc[mt][nt][3];
            if (RELU) {
                v0 = v0 > 0.f ? v0 : 0.f;  v1 = v1 > 0.f ? v1 : 0.f;
                v2 = v2 > 0.f ? v2 : 0.f;  v3 = v3 > 0.f ? v3 : 0.f;
            }
            if (gm < M) {
                if (gn     < N) Cb[(long)gm * N + gn    ] = v0;
                if (gn + 1 < N) Cb[(long)gm * N + gn + 1] = v1;
            }
            if (gm + 8 < M) {
                if (gn     < N) Cb[(long)(gm + 8) * N + gn    ] = v2;
                if (gn + 1 < N) Cb[(long)(gm + 8) * N + gn + 1] = v3;
            }
        }
    }
}

// ---------------- row stats: max + 1/sumexp for BOTH attentions + sum(A^2) ----------------
__global__ void rowstat_k(const float* __restrict__ A,
                          const float* __restrict__ f1z, const float* __restrict__ f2z,
                          const float* __restrict__ f1s, const float* __restrict__ f2s,
                          float* __restrict__ mz, float* __restrict__ iz,
                          float* __restrict__ ms, float* __restrict__ is_, int N)
{
    int row = blockIdx.x;          // b*N + i
    int b = row / N;
    const float* Ar = A + (size_t)row * N;
    const float* f2zb = f2z + (size_t)b * N;
    const float* f2sb = f2s + (size_t)b * N;
    float fz = f1z[row], fs = f1s[row];
    int t = threadIdx.x;
    float ez[4], es[4];
    float mzl = -1e30f, msl = -1e30f;
    double ss = 0.0;
#pragma unroll
    for (int it = 0; it < 4; it++) {
        int j = t + it * 256;
        float vz = -9e15f, vs = -9e15f;
        if (j < N) {
            float a = Ar[j];
            ss += (double)a * (double)a;
            bool on = a > 0.f;
            float xz = fz + f2zb[j];
            float xs = fs + f2sb[j];
            float lz = (xz > 0.f) ? xz : 0.2f * xz;
            float ls = (xs > 0.f) ? xs : 0.2f * xs;
            vz = on ? lz : -9e15f;
            vs = on ? ls : -9e15f;
        }
        ez[it] = vz; es[it] = vs;
        mzl = fmaxf(mzl, vz); msl = fmaxf(msl, vs);
    }
    __shared__ float sh[256];
    sh[t] = mzl; __syncthreads();
    for (int s = 128; s > 0; s >>= 1) { if (t < s) sh[t] = fmaxf(sh[t], sh[t + s]); __syncthreads(); }
    float Mz = sh[0]; __syncthreads();
    sh[t] = msl; __syncthreads();
    for (int s = 128; s > 0; s >>= 1) { if (t < s) sh[t] = fmaxf(sh[t], sh[t + s]); __syncthreads(); }
    float Ms = sh[0]; __syncthreads();

    float sz = 0.f, ssum = 0.f;
#pragma unroll
    for (int it = 0; it < 4; it++) {
        int j = t + it * 256;
        if (j < N) { sz += __expf(ez[it] - Mz); ssum += __expf(es[it] - Ms); }
    }
    sh[t] = sz; __syncthreads();
    for (int s = 128; s > 0; s >>= 1) { if (t < s) sh[t] += sh[t + s]; __syncthreads(); }
    float Sz = sh[0]; __syncthreads();
    sh[t] = ssum; __syncthreads();
    for (int s = 128; s > 0; s >>= 1) { if (t < s) sh[t] += sh[t + s]; __syncthreads(); }
    float Ss = sh[0]; __syncthreads();

    __shared__ double dh[256];
    dh[t] = ss; __syncthreads();
    for (int s = 128; s > 0; s >>= 1) { if (t < s) dh[t] += dh[t + s]; __syncthreads(); }

    if (t == 0) {
        mz[row] = Mz; iz[row] = 1.f / Sz;
        ms[row] = Ms; is_[row] = 1.f / Ss;
        atomicAdd(&g_tot, dh[0]);
    }
}

// ---------------- f1/f2 = Wh . a[:F], Wh . a[F:] (warp per row) ----------------
__global__ void fvec_k(const float* __restrict__ Wh, const float* __restrict__ a,
                       float* __restrict__ f1, float* __restrict__ f2,
                       int rows, int F)
{
    int w = (blockIdx.x * blockDim.x + threadIdx.x) >> 5;
    int lane = threadIdx.x & 31;
    if (w >= rows) return;
    const float* p = Wh + (size_t)w * F;
    float s1 = 0.f, s2 = 0.f;
    for (int f = lane; f < F; f += 32) {
        float v = p[f];
        s1 += v * a[f];
        s2 += v * a[F + f];
    }
#pragma unroll
    for (int o = 16; o > 0; o >>= 1) {
        s1 += __shfl_down_sync(0xffffffffu, s1, o);
        s2 += __shfl_down_sync(0xffffffffu, s2, o);
    }
    if (lane == 0) { f1[w] = s1; f2[w] = s2; }
}

// ---------------- softmax over c (warp per row) + entropy accumulation ----------------
__global__ void softmax_c_ent(float* __restrict__ S, int rows, int c, double inv_rows)
{
    int w = (blockIdx.x * blockDim.x + threadIdx.x) >> 5;
    int lane = threadIdx.x & 31;
    if (w >= rows) return;
    float* p = S + (size_t)w * c;
    float v[2] = {-1e30f, -1e30f};
    float m = -1e30f;
#pragma unroll
    for (int i = 0; i < 2; i++) {
        int f = lane + 32 * i;
        if (f < c) { v[i] = p[f]; m = fmaxf(m, v[i]); }
    }
#pragma unroll
    for (int o = 16; o > 0; o >>= 1) m = fmaxf(m, __shfl_xor_sync(0xffffffffu, m, o));
    float s = 0.f;
#pragma unroll
    for (int i = 0; i < 2; i++) {
        int f = lane + 32 * i;
        if (f < c) { v[i] = __expf(v[i] - m); s += v[i]; }
    }
#pragma unroll
    for (int o = 16; o > 0; o >>= 1) s += __shfl_xor_sync(0xffffffffu, s, o);
    float inv = 1.f / s;
    double erow = 0.0;
#pragma unroll
    for (int i = 0; i < 2; i++) {
        int f = lane + 32 * i;
        if (f < c) {
            float q = v[i] * inv;
            p[f] = q;
            erow += -(double)q * (double)logf(q + 1e-15f);
        }
    }
#pragma unroll
    for (int o = 16; o > 0; o >>= 1) erow += __shfl_down_sync(0xffffffffu, erow, o);
    if (lane == 0) atomicAdd(&g_ent, erow * inv_rows);
}

// ---------------- loss reductions ----------------
__global__ void accum_sq(const float* __restrict__ x, long n)
{
    __shared__ double sh[256];
    long i = (long)blockIdx.x * blockDim.x + threadIdx.x;
    double s = 0.0;
    long stride = (long)gridDim.x * blockDim.x;
    for (; i < n; i += stride) { double v = x[i]; s += v * v; }
    sh[threadIdx.x] = s; __syncthreads();
    for (int r = 128; r > 0; r >>= 1) { if (threadIdx.x < r) sh[threadIdx.x] += sh[threadIdx.x + r]; __syncthreads(); }
    if (threadIdx.x == 0) atomicAdd(&g_tot, sh[0]);
}

__global__ void trace_neg2(const float* __restrict__ Anew, int total, int c)
{
    int t = blockIdx.x * blockDim.x + threadIdx.x;
    if (t >= total) return;
    int b = t / c, j = t % c;
    atomicAdd(&g_tot, -2.0 * (double)Anew[((long)b * c + j) * c + j]);
}

__global__ void k_zero_losses() { g_link = 0.0; g_ent = 0.0; g_tot = 0.0; }
__global__ void k_zero_tot()    { g_tot = 0.0; }
__global__ void k_finalize_link(double denom)
{
    double v = g_tot;
    g_link += sqrt(v > 0.0 ? v : 0.0) / denom;
}

// ---------------- final dense + output assembly ----------------
__global__ void final_logits(const float* __restrict__ X3, const float* __restrict__ Wd,
                             const float* __restrict__ bd, float* __restrict__ out, int out_size)
{
    int t = blockIdx.x * blockDim.x + threadIdx.x;
    if (t >= BATCH * NCLASS) return;
    int b = t / NCLASS, cls = t % NCLASS;
    float s = bd[cls];
    const float* xr = X3 + (long)b * 256;
    for (int f = 0; f < 256; f++) s += xr[f] * Wd[f * NCLASS + cls];
    if (t < out_size) out[t] = s;
}

__global__ void write_tail(const float* __restrict__ A3, float* __restrict__ out, int out_size)
{
    int t = threadIdx.x;
    if (t < BATCH && 160 + t < out_size) out[160 + t] = A3[t];
    if (t == 0) {
        if (176 < out_size) out[176] = (float)g_link;
        if (177 < out_size) out[177] = (float)g_ent;
    }
}

static int grid_for(long n) { long b = (n + 255) / 256; return (int)(b < 2048 ? b : 2048); }
#define NOF nullptr, nullptr, nullptr, nullptr

// One GAT+pool layer.
static void run_layer(const float* X, const float* A,
                      const float* Wg, const float* ag, const float* Ws, const float* as_,
                      float* Xout, float* Aout,
                      int N_, int Fin, int Fz, int c,
                      float* whz, float* whs, float* z, float* s, float* t, float* gg,
                      float* f1z, float* f2z, float* f1s, float* f2s,
                      float* mz, float* iz, float* ms, float* is_)
{
    int rows = BATCH * N_;
    long sX = (long)N_ * Fin;

    // Wh_z = X @ Wg ; Wh_s = X @ Ws
    {
        dim3 g((Fz + 127) / 128, (N_ + 127) / 128, BATCH);
        mma_k<128, 128, AM_NN, false><<<g, 256>>>(X, Wg, whz, N_, Fz, Fin, sX, 0, (long)N_ * Fz, NOF);
    }
    {
        dim3 g((c + 63) / 64, (N_ + 127) / 128, BATCH);
        mma_k<128, 64, AM_NN, false><<<g, 256>>>(X, Ws, whs, N_, c, Fin, sX, 0, (long)N_ * c, NOF);
    }

    int fblocks = (rows * 32 + 255) / 256;
    fvec_k<<<fblocks, 256>>>(whz, ag, f1z, f2z, rows, Fz);
    fvec_k<<<fblocks, 256>>>(whs, as_, f1s, f2s, rows, c);

    // stats pass: one read of A, both attentions + sum(A^2)
    k_zero_tot<<<1, 1>>>();
    rowstat_k<<<rows, 256>>>(A, f1z, f2z, f1s, f2s, mz, iz, ms, is_, N_);

    // Z = relu(P_z @ Wh_z); S_pre = relu(P_s @ Wh_s) — P on the fly, tensor cores
    {
        dim3 g((Fz + 127) / 128, (N_ + 127) / 128, BATCH);
        mma_k<128, 128, AM_FUSED, true><<<g, 256>>>(A, whz, z, N_, Fz, N_,
            (long)N_ * N_, (long)N_ * Fz, (long)N_ * Fz, f1z, f2z, mz, iz);
    }
    {
        dim3 g((c + 63) / 64, (N_ + 127) / 128, BATCH);
        mma_k<128, 64, AM_FUSED, true><<<g, 256>>>(A, whs, s, N_, c, N_,
            (long)N_ * N_, (long)N_ * c, (long)N_ * c, f1s, f2s, ms, is_);
    }
    softmax_c_ent<<<(rows + 7) / 8, 256>>>(s, rows, c, 1.0 / (double)rows);

    // T = S^T A
    {
        dim3 g((N_ + 127) / 128, (c + 63) / 64, BATCH);
        mma_k<64, 128, AM_TN, false><<<g, 256>>>(s, A, t, c, N_, N_,
            (long)N_ * c, (long)N_ * N_, (long)c * N_, NOF);
    }
    // A_new = T @ S
    {
        dim3 g((c + 127) / 128, (c + 63) / 64, BATCH);
        mma_k<64, 128, AM_NN, false><<<g, 256>>>(t, s, Aout, c, c, N_,
            (long)c * N_, (long)N_ * c, (long)c * c, NOF);
    }
    // X_new = S^T Z
    {
        dim3 g((Fz + 127) / 128, (c + 63) / 64, BATCH);
        mma_k<64, 128, AM_TN, false><<<g, 256>>>(s, z, Xout, c, Fz, N_,
            (long)N_ * c, (long)N_ * Fz, (long)c * Fz, NOF);
    }
    // G = S^T S
    {
        dim3 g((c + 127) / 128, (c + 63) / 64, BATCH);
        mma_k<64, 128, AM_TN, false><<<g, 256>>>(s, s, gg, c, c, N_,
            (long)N_ * c, (long)N_ * c, (long)c * c, NOF);
    }

    // link loss: ||A - S S^T||_F^2 = sum(A^2) - 2 tr(S^T A S) + ||S^T S||_F^2
    trace_neg2<<<(BATCH * c + 255) / 256, 256>>>(Aout, BATCH * c, c);
    long nG = (long)BATCH * c * c;
    accum_sq<<<grid_for(nG), 256>>>(gg, nG);
    long nA = (long)BATCH * N_ * N_;
    k_finalize_link<<<1, 1>>>((double)nA);
}

extern "C" void kernel_launch(void* const* d_in, const int* in_sizes, int n_in,
                              void* d_out, int out_size)
{
    (void)in_sizes; (void)n_in;
    const float* X  = (const float*)d_in[0];
    const float* A  = (const float*)d_in[1];
    const float* Wg[3]  = {(const float*)d_in[2], (const float*)d_in[6],  (const float*)d_in[10]};
    const float* ag[3]  = {(const float*)d_in[3], (const float*)d_in[7],  (const float*)d_in[11]};
    const float* Ws[3]  = {(const float*)d_in[4], (const float*)d_in[8],  (const float*)d_in[12]};
    const float* as_[3] = {(const float*)d_in[5], (const float*)d_in[9],  (const float*)d_in[13]};
    const float* Wd = (const float*)d_in[14];
    const float* bd = (const float*)d_in[15];
    float* out = (float*)d_out;

    float *whz, *whs, *z, *s, *t, *gg;
    float *xp, *ap, *xq, *aq, *x3, *a3;
    float *f1z, *f2z, *f1s, *f2s, *mz, *iz, *ms, *is_;
    cudaGetSymbolAddress((void**)&whz, g_Whz);
    cudaGetSymbolAddress((void**)&whs, g_Whs);
    cudaGetSymbolAddress((void**)&z,   g_Zb);
    cudaGetSymbolAddress((void**)&s,   g_Sb);
    cudaGetSymbolAddress((void**)&t,   g_Tb);
    cudaGetSymbolAddress((void**)&gg,  g_Gb);
    cudaGetSymbolAddress((void**)&xp,  g_Xp);
    cudaGetSymbolAddress((void**)&ap,  g_Ap);
    cudaGetSymbolAddress((void**)&xq,  g_Xq);
    cudaGetSymbolAddress((void**)&aq,  g_Aq);
    cudaGetSymbolAddress((void**)&x3,  g_X3);
    cudaGetSymbolAddress((void**)&a3,  g_A3);
    cudaGetSymbolAddress((void**)&f1z, g_f1z);
    cudaGetSymbolAddress((void**)&f2z, g_f2z);
    cudaGetSymbolAddress((void**)&f1s, g_f1s);
    cudaGetSymbolAddress((void**)&f2s, g_f2s);
    cudaGetSymbolAddress((void**)&mz,  g_mz);
    cudaGetSymbolAddress((void**)&iz,  g_iz);
    cudaGetSymbolAddress((void**)&ms,  g_ms);
    cudaGetSymbolAddress((void**)&is_, g_is);

    k_zero_losses<<<1, 1>>>();

    // layer 0: N=1024, Fin=128, Fz=256, c=64
    run_layer(X, A, Wg[0], ag[0], Ws[0], as_[0], xp, ap,
              1024, 128, 256, 64, whz, whs, z, s, t, gg,
              f1z, f2z, f1s, f2s, mz, iz, ms, is_);
    // layer 1: N=64, Fin=256, Fz=256, c=8
    run_layer(xp, ap, Wg[1], ag[1], Ws[1], as_[1], xq, aq,
              64, 256, 256, 8, whz, whs, z, s, t, gg,
              f1z, f2z, f1s, f2s, mz, iz, ms, is_);
    // layer 2: N=8, Fin=256, Fz=256, c=1
    run_layer(xq, aq, Wg[2], ag[2], Ws[2], as_[2], x3, a3,
              8, 256, 256, 1, whz, whs, z, s, t, gg,
              f1z, f2z, f1s, f2s, mz, iz, ms, is_);

    final_logits<<<1, 192>>>(x3, Wd, bd, out, out_size);
    write_tail<<<1, 32>>>(a3, out, out_size);
}

// round 6
// speedup vs baseline: 2.2604x; 1.2497x over previous
#include <cuda_runtime.h>
#include <cuda_bf16.h>
#include <math.h>
#include <stdint.h>

#define BATCH 16
#define NCLASS 10

// ---------------- scratch (static __device__, allocation-free) ----------------
__device__ float g_Whz[(size_t)BATCH * 1024 * 256];
__device__ float g_Whs[(size_t)BATCH * 1024 * 64];
__device__ float g_Zb [(size_t)BATCH * 1024 * 256];
__device__ float g_Sb [(size_t)BATCH * 1024 * 64];
__device__ float g_Tb [(size_t)BATCH * 64 * 1024];
__device__ float g_Gb [(size_t)BATCH * 64 * 64];
__device__ float g_Xp [(size_t)BATCH * 64 * 256];
__device__ float g_Ap [(size_t)BATCH * 64 * 64];
__device__ float g_Xq [(size_t)BATCH * 8 * 256];
__device__ float g_Aq [(size_t)BATCH * 8 * 8];
__device__ float g_X3 [(size_t)BATCH * 256];
__device__ float g_A3 [(size_t)BATCH];
__device__ float g_f1z[BATCH * 1024];
__device__ float g_f2z[BATCH * 1024];
__device__ float g_f1s[BATCH * 1024];
__device__ float g_f2s[BATCH * 1024];
__device__ float g_mz [BATCH * 1024];
__device__ float g_iz [BATCH * 1024];
__device__ float g_ms [BATCH * 1024];
__device__ float g_is [BATCH * 1024];
__device__ double g_link, g_ent, g_tot;

// pack two floats' bf16 hi/lo splits into bf16x2 words
__device__ __forceinline__ void pack_split(float x0, float x1, uint32_t& hw, uint32_t& lw) {
    __nv_bfloat16 h0 = __float2bfloat16_rn(x0);
    __nv_bfloat16 h1 = __float2bfloat16_rn(x1);
    float r0 = x0 - __bfloat162float(h0);
    float r1 = x1 - __bfloat162float(h1);
    __nv_bfloat16 l0 = __float2bfloat16_rn(r0);
    __nv_bfloat16 l1 = __float2bfloat16_rn(r1);
    hw = (uint32_t)__bfloat16_as_ushort(h0) | ((uint32_t)__bfloat16_as_ushort(h1) << 16);
    lw = (uint32_t)__bfloat16_as_ushort(l0) | ((uint32_t)__bfloat16_as_ushort(l1) << 16);
}

#define AM_NN    0
#define AM_TN    1
#define AM_FUSED 2

// ---------------- 3xBF16 split warp-MMA GEMM (near-fp32 accurate) ----------------
// C[b] = op(A[b]) * B[b] via mma.sync.m16n8k16.bf16 with hi/lo split:
//   C += Ahi*Bhi + Ahi*Blo + Alo*Bhi     (lo*lo dropped, ~2^-18 relative)
// EXB: B operand is exactly bf16-representable (adjacency 0/1) -> skip Ahi*Blo.
// AM_NN: A is MxK row-major. AM_TN: A stored KxM (compute A^T B).
// AM_FUSED: attention P generated on the fly from adjacency + f1/f2/rm/ri.
// B is KxN row-major. 8 warps: 2 (m) x 4 (n).
template<int BM, int BN, int AM, bool RELU, bool EXB>
__global__ __launch_bounds__(256)
void mma_k(const float* __restrict__ Ag, const float* __restrict__ Bg,
           float* __restrict__ Cg, int M, int N, int K,
           long sA, long sB, long sC,
           const float* __restrict__ f1, const float* __restrict__ f2,
           const float* __restrict__ rm, const float* __restrict__ ri)
{
    constexpr int BK  = 16;
    constexpr int KP  = 8;            // k-pairs per stage
    constexpr int PAD = 8;
    constexpr int WM  = BM / 2;
    constexpr int WN  = BN / 4;
    constexpr int MT  = WM / 16;
    constexpr int NT  = WN / 8;
    constexpr int APL = (BM * KP) / 256;
    constexpr int BPL = (BN * KP) / 256;

    __shared__ uint32_t AsH[KP][BM + PAD];
    __shared__ uint32_t AsL[KP][BM + PAD];
    __shared__ uint32_t BsH[KP][BN + PAD];
    __shared__ uint32_t BsL[EXB ? 1 : KP][BN + PAD];
    __shared__ float s_f1[BM], s_m[BM], s_i[BM];

    const int b = blockIdx.z;
    const float* Ab = Ag + (long)b * sA;
    const float* Bb = Bg + (long)b * sB;
    float* Cb = Cg + (long)b * sC;

    const int bm = blockIdx.y * BM, bn = blockIdx.x * BN;
    const int tid  = threadIdx.x;
    const int warp = tid >> 5, lane = tid & 31;
    const int wm = (warp >> 2) * WM, wn = (warp & 3) * WN;
    const int lg = lane >> 2, lt = lane & 3;

    const float* f2b = nullptr;
    if (AM == AM_FUSED) {
        f2b = f2 + (long)b * K;
        const float* f1b = f1 + (long)b * K;
        const float* rmb = rm + (long)b * K;
        const float* rib = ri + (long)b * K;
        for (int i = tid; i < BM; i += 256) {
            int gi = bm + i;
            if (gi < M) { s_f1[i] = f1b[gi]; s_m[i] = rmb[gi]; s_i[i] = rib[gi]; }
            else        { s_f1[i] = 0.f; s_m[i] = 0.f; s_i[i] = 1.f; }
        }
    }

    float acc[MT][NT][4];
#pragma unroll
    for (int mt = 0; mt < MT; mt++)
#pragma unroll
        for (int nt = 0; nt < NT; nt++)
#pragma unroll
            for (int q = 0; q < 4; q++) acc[mt][nt][q] = 0.f;

    float2 rA[APL], rB[BPL];
    float2 rF[(AM == AM_FUSED) ? APL : 1];

    auto loadA = [&](int k0) {
#pragma unroll
        for (int t = 0; t < APL; t++) {
            int idx = tid + 256 * t;
            if (AM == AM_TN) {
                int m = idx % BM, kp = idx / BM;
                int gm = bm + m, gk = k0 + 2 * kp;
                float x0 = (gm < M && gk     < K) ? Ab[(long)gk * M + gm]       : 0.f;
                float x1 = (gm < M && gk + 1 < K) ? Ab[(long)(gk + 1) * M + gm] : 0.f;
                rA[t] = make_float2(x0, x1);
            } else {
                int kp = idx & 7, m = idx >> 3;
                int gm = bm + m, gk = k0 + 2 * kp;
                float x0 = 0.f, x1 = 0.f;
                if (gm < M) {
                    if (gk + 1 < K) {
                        float2 v = *reinterpret_cast<const float2*>(&Ab[(long)gm * K + gk]);
                        x0 = v.x; x1 = v.y;
                    } else if (gk < K) {
                        x0 = Ab[(long)gm * K + gk];
                    }
                }
                rA[t] = make_float2(x0, x1);
                if (AM == AM_FUSED) {
                    float fa = 0.f, fb = 0.f;
                    if (gk + 1 < K) {
                        float2 v = *reinterpret_cast<const float2*>(&f2b[gk]);
                        fa = v.x; fb = v.y;
                    } else if (gk < K) {
                        fa = f2b[gk];
                    }
                    rF[t] = make_float2(fa, fb);
                }
            }
        }
    };
    auto loadB = [&](int k0) {
#pragma unroll
        for (int t = 0; t < BPL; t++) {
            int idx = tid + 256 * t;
            int n = idx % BN, kp = idx / BN;
            int gn = bn + n, gk = k0 + 2 * kp;
            float x0 = (gn < N && gk     < K) ? Bb[(long)gk * N + gn]       : 0.f;
            float x1 = (gn < N && gk + 1 < K) ? Bb[(long)(gk + 1) * N + gn] : 0.f;
            rB[t] = make_float2(x0, x1);
        }
    };
    auto storeAB = [&](int k0) {
#pragma unroll
        for (int t = 0; t < APL; t++) {
            int idx = tid + 256 * t;
            int kp, m;
            if (AM == AM_TN) { m = idx % BM; kp = idx / BM; }
            else             { kp = idx & 7; m = idx >> 3; }
            float x0 = rA[t].x, x1 = rA[t].y;
            if (AM == AM_FUSED) {
                int gk = k0 + 2 * kp;
                float e0 = s_f1[m] + rF[t].x; e0 = (e0 > 0.f) ? e0 : 0.2f * e0;
                if (!(x0 > 0.f)) e0 = -9e15f;
                float e1 = s_f1[m] + rF[t].y; e1 = (e1 > 0.f) ? e1 : 0.2f * e1;
                if (!(x1 > 0.f)) e1 = -9e15f;
                x0 = (gk     < K) ? __expf(e0 - s_m[m]) * s_i[m] : 0.f;
                x1 = (gk + 1 < K) ? __expf(e1 - s_m[m]) * s_i[m] : 0.f;
            }
            uint32_t hw, lw; pack_split(x0, x1, hw, lw);
            AsH[kp][m] = hw; AsL[kp][m] = lw;
        }
#pragma unroll
        for (int t = 0; t < BPL; t++) {
            int idx = tid + 256 * t;
            int n = idx % BN, kp = idx / BN;
            uint32_t hw, lw; pack_split(rB[t].x, rB[t].y, hw, lw);
            BsH[kp][n] = hw;
            if (!EXB) BsL[kp][n] = lw;
        }
    };

    loadA(0); loadB(0);
    __syncthreads();                      // covers s_f1/s_m/s_i init too

    for (int k0 = 0; k0 < K; k0 += BK) {
        storeAB(k0);
        __syncthreads();
        if (k0 + BK < K) { loadA(k0 + BK); loadB(k0 + BK); }   // prefetch under compute

        uint32_t ah[MT][4], al[MT][4], bh[NT][2], bl[NT][2];
#pragma unroll
        for (int mt = 0; mt < MT; mt++) {
            int r = wm + mt * 16;
            ah[mt][0] = AsH[lt    ][r + lg];
            ah[mt][1] = AsH[lt    ][r + lg + 8];
            ah[mt][2] = AsH[lt + 4][r + lg];
            ah[mt][3] = AsH[lt + 4][r + lg + 8];
            al[mt][0] = AsL[lt    ][r + lg];
            al[mt][1] = AsL[lt    ][r + lg + 8];
            al[mt][2] = AsL[lt + 4][r + lg];
            al[mt][3] = AsL[lt + 4][r + lg + 8];
        }
#pragma unroll
        for (int nt = 0; nt < NT; nt++) {
            int cidx = wn + nt * 8 + lg;
            bh[nt][0] = BsH[lt    ][cidx];
            bh[nt][1] = BsH[lt + 4][cidx];
            if (!EXB) {
                bl[nt][0] = BsL[lt    ][cidx];
                bl[nt][1] = BsL[lt + 4][cidx];
            }
        }
#define MMA_STEP(AF, BF)                                                        \
        asm volatile(                                                           \
            "mma.sync.aligned.m16n8k16.row.col.f32.bf16.bf16.f32 "              \
            "{%0,%1,%2,%3}, {%4,%5,%6,%7}, {%8,%9}, {%0,%1,%2,%3};"             \
            : "+f"(acc[mt][nt][0]), "+f"(acc[mt][nt][1]),                       \
              "+f"(acc[mt][nt][2]), "+f"(acc[mt][nt][3])                        \
            : "r"(AF[mt][0]), "r"(AF[mt][1]), "r"(AF[mt][2]), "r"(AF[mt][3]),   \
              "r"(BF[nt][0]), "r"(BF[nt][1]))
#pragma unroll
        for (int mt = 0; mt < MT; mt++)
#pragma unroll
            for (int nt = 0; nt < NT; nt++) {
                if (!EXB) MMA_STEP(ah, bl);   // cross terms first (small)
                MMA_STEP(al, bh);
                MMA_STEP(ah, bh);             // main term
            }
#undef MMA_STEP
        __syncthreads();
    }

    // epilogue: c0:(g,2lt) c1:(g,2lt+1) c2:(g+8,2lt) c3:(g+8,2lt+1)
#pragma unroll
    for (int mt = 0; mt < MT; mt++) {
#pragma unroll
        for (int nt = 0; nt < NT; nt++) {
            int gm = bm + wm + mt * 16 + lg;
            int gn = bn + wn + nt * 8 + 2 * lt;
            float v0 = acc[mt][nt][0], v1 = acc[mt][nt][1];
            float v2 = acc[mt][nt][2], v3 = acc[mt][nt][3];
            if (RELU) {
                v0 = v0 > 0.f ? v0 : 0.f;  v1 = v1 > 0.f ? v1 : 0.f;
                v2 = v2 > 0.f ? v2 : 0.f;  v3 = v3 > 0.f ? v3 : 0.f;
            }
            if (gm < M) {
                if (gn     < N) Cb[(long)gm * N + gn    ] = v0;
                if (gn + 1 < N) Cb[(long)gm * N + gn + 1] = v1;
            }
            if (gm + 8 < M) {
                if (gn     < N) Cb[(long)(gm + 8) * N + gn    ] = v2;
                if (gn + 1 < N) Cb[(long)(gm + 8) * N + gn + 1] = v3;
            }
        }
    }
}

// ---------------- row stats: max + 1/sumexp for BOTH attentions + sum(A^2) ----------------
__global__ void rowstat_k(const float* __restrict__ A,
                          const float* __restrict__ f1z, const float* __restrict__ f2z,
                          const float* __restrict__ f1s, const float* __restrict__ f2s,
                          float* __restrict__ mz, float* __restrict__ iz,
                          float* __restrict__ ms, float* __restrict__ is_, int N)
{
    int row = blockIdx.x;          // b*N + i
    int b = row / N;
    const float* Ar = A + (size_t)row * N;
    const float* f2zb = f2z + (size_t)b * N;
    const float* f2sb = f2s + (size_t)b * N;
    float fz = f1z[row], fs = f1s[row];
    int t = threadIdx.x;
    float ez[4], es[4];
    float mzl = -1e30f, msl = -1e30f;
    double ss = 0.0;
#pragma unroll
    for (int it = 0; it < 4; it++) {
        int j = t + it * 256;
        float vz = -9e15f, vs = -9e15f;
        if (j < N) {
            float a = Ar[j];
            ss += (double)a * (double)a;
            bool on = a > 0.f;
            float xz = fz + f2zb[j];
            float xs = fs + f2sb[j];
            float lz = (xz > 0.f) ? xz : 0.2f * xz;
            float ls = (xs > 0.f) ? xs : 0.2f * xs;
            vz = on ? lz : -9e15f;
            vs = on ? ls : -9e15f;
        }
        ez[it] = vz; es[it] = vs;
        mzl = fmaxf(mzl, vz); msl = fmaxf(msl, vs);
    }
    __shared__ float sh[256];
    sh[t] = mzl; __syncthreads();
    for (int s = 128; s > 0; s >>= 1) { if (t < s) sh[t] = fmaxf(sh[t], sh[t + s]); __syncthreads(); }
    float Mz = sh[0]; __syncthreads();
    sh[t] = msl; __syncthreads();
    for (int s = 128; s > 0; s >>= 1) { if (t < s) sh[t] = fmaxf(sh[t], sh[t + s]); __syncthreads(); }
    float Ms = sh[0]; __syncthreads();

    float sz = 0.f, ssum = 0.f;
#pragma unroll
    for (int it = 0; it < 4; it++) {
        int j = t + it * 256;
        if (j < N) { sz += __expf(ez[it] - Mz); ssum += __expf(es[it] - Ms); }
    }
    sh[t] = sz; __syncthreads();
    for (int s = 128; s > 0; s >>= 1) { if (t < s) sh[t] += sh[t + s]; __syncthreads(); }
    float Sz = sh[0]; __syncthreads();
    sh[t] = ssum; __syncthreads();
    for (int s = 128; s > 0; s >>= 1) { if (t < s) sh[t] += sh[t + s]; __syncthreads(); }
    float Ss = sh[0]; __syncthreads();

    __shared__ double dh[256];
    dh[t] = ss; __syncthreads();
    for (int s = 128; s > 0; s >>= 1) { if (t < s) dh[t] += dh[t + s]; __syncthreads(); }

    if (t == 0) {
        mz[row] = Mz; iz[row] = 1.f / Sz;
        ms[row] = Ms; is_[row] = 1.f / Ss;
        atomicAdd(&g_tot, dh[0]);
    }
}

// ---------------- f1/f2 = Wh . a[:F], Wh . a[F:] (warp per row) ----------------
__global__ void fvec_k(const float* __restrict__ Wh, const float* __restrict__ a,
                       float* __restrict__ f1, float* __restrict__ f2,
                       int rows, int F)
{
    int w = (blockIdx.x * blockDim.x + threadIdx.x) >> 5;
    int lane = threadIdx.x & 31;
    if (w >= rows) return;
    const float* p = Wh + (size_t)w * F;
    float s1 = 0.f, s2 = 0.f;
    for (int f = lane; f < F; f += 32) {
        float v = p[f];
        s1 += v * a[f];
        s2 += v * a[F + f];
    }
#pragma unroll
    for (int o = 16; o > 0; o >>= 1) {
        s1 += __shfl_down_sync(0xffffffffu, s1, o);
        s2 += __shfl_down_sync(0xffffffffu, s2, o);
    }
    if (lane == 0) { f1[w] = s1; f2[w] = s2; }
}

// ---------------- softmax over c (warp per row) + entropy accumulation ----------------
__global__ void softmax_c_ent(float* __restrict__ S, int rows, int c, double inv_rows)
{
    int w = (blockIdx.x * blockDim.x + threadIdx.x) >> 5;
    int lane = threadIdx.x & 31;
    if (w >= rows) return;
    float* p = S + (size_t)w * c;
    float v[2] = {-1e30f, -1e30f};
    float m = -1e30f;
#pragma unroll
    for (int i = 0; i < 2; i++) {
        int f = lane + 32 * i;
        if (f < c) { v[i] = p[f]; m = fmaxf(m, v[i]); }
    }
#pragma unroll
    for (int o = 16; o > 0; o >>= 1) m = fmaxf(m, __shfl_xor_sync(0xffffffffu, m, o));
    float s = 0.f;
#pragma unroll
    for (int i = 0; i < 2; i++) {
        int f = lane + 32 * i;
        if (f < c) { v[i] = __expf(v[i] - m); s += v[i]; }
    }
#pragma unroll
    for (int o = 16; o > 0; o >>= 1) s += __shfl_xor_sync(0xffffffffu, s, o);
    float inv = 1.f / s;
    double erow = 0.0;
#pragma unroll
    for (int i = 0; i < 2; i++) {
        int f = lane + 32 * i;
        if (f < c) {
            float q = v[i] * inv;
            p[f] = q;
            erow += -(double)q * (double)logf(q + 1e-15f);
        }
    }
#pragma unroll
    for (int o = 16; o > 0; o >>= 1) erow += __shfl_down_sync(0xffffffffu, erow, o);
    if (lane == 0) atomicAdd(&g_ent, erow * inv_rows);
}

// ---------------- loss reductions ----------------
__global__ void accum_sq(const float* __restrict__ x, long n)
{
    __shared__ double sh[256];
    long i = (long)blockIdx.x * blockDim.x + threadIdx.x;
    double s = 0.0;
    long stride = (long)gridDim.x * blockDim.x;
    for (; i < n; i += stride) { double v = x[i]; s += v * v; }
    sh[threadIdx.x] = s; __syncthreads();
    for (int r = 128; r > 0; r >>= 1) { if (threadIdx.x < r) sh[threadIdx.x] += sh[threadIdx.x + r]; __syncthreads(); }
    if (threadIdx.x == 0) atomicAdd(&g_tot, sh[0]);
}

__global__ void trace_neg2(const float* __restrict__ Anew, int total, int c)
{
    int t = blockIdx.x * blockDim.x + threadIdx.x;
    if (t >= total) return;
    int b = t / c, j = t % c;
    atomicAdd(&g_tot, -2.0 * (double)Anew[((long)b * c + j) * c + j]);
}

__global__ void k_zero_losses() { g_link = 0.0; g_ent = 0.0; g_tot = 0.0; }
__global__ void k_zero_tot()    { g_tot = 0.0; }
__global__ void k_finalize_link(double denom)
{
    double v = g_tot;
    g_link += sqrt(v > 0.0 ? v : 0.0) / denom;
}

// ---------------- final dense + output assembly ----------------
__global__ void final_logits(const float* __restrict__ X3, const float* __restrict__ Wd,
                             const float* __restrict__ bd, float* __restrict__ out, int out_size)
{
    int t = blockIdx.x * blockDim.x + threadIdx.x;
    if (t >= BATCH * NCLASS) return;
    int b = t / NCLASS, cls = t % NCLASS;
    float s = bd[cls];
    const float* xr = X3 + (long)b * 256;
    for (int f = 0; f < 256; f++) s += xr[f] * Wd[f * NCLASS + cls];
    if (t < out_size) out[t] = s;
}

__global__ void write_tail(const float* __restrict__ A3, float* __restrict__ out, int out_size)
{
    int t = threadIdx.x;
    if (t < BATCH && 160 + t < out_size) out[160 + t] = A3[t];
    if (t == 0) {
        if (176 < out_size) out[176] = (float)g_link;
        if (177 < out_size) out[177] = (float)g_ent;
    }
}

static int grid_for(long n) { long b = (n + 255) / 256; return (int)(b < 2048 ? b : 2048); }
#define NOF nullptr, nullptr, nullptr, nullptr

// One GAT+pool layer.
static void run_layer(const float* X, const float* A,
                      const float* Wg, const float* ag, const float* Ws, const float* as_,
                      float* Xout, float* Aout,
                      int N_, int Fin, int Fz, int c,
                      float* whz, float* whs, float* z, float* s, float* t, float* gg,
                      float* f1z, float* f2z, float* f1s, float* f2s,
                      float* mz, float* iz, float* ms, float* is_)
{
    int rows = BATCH * N_;
    long sX = (long)N_ * Fin;

    // Wh_z = X @ Wg ; Wh_s = X @ Ws
    {
        dim3 g((Fz + 127) / 128, (N_ + 127) / 128, BATCH);
        mma_k<128, 128, AM_NN, false, false><<<g, 256>>>(X, Wg, whz, N_, Fz, Fin, sX, 0, (long)N_ * Fz, NOF);
    }
    {
        dim3 g((c + 63) / 64, (N_ + 127) / 128, BATCH);
        mma_k<128, 64, AM_NN, false, false><<<g, 256>>>(X, Ws, whs, N_, c, Fin, sX, 0, (long)N_ * c, NOF);
    }

    int fblocks = (rows * 32 + 255) / 256;
    fvec_k<<<fblocks, 256>>>(whz, ag, f1z, f2z, rows, Fz);
    fvec_k<<<fblocks, 256>>>(whs, as_, f1s, f2s, rows, c);

    // stats pass: one read of A, both attentions + sum(A^2)
    k_zero_tot<<<1, 1>>>();
    rowstat_k<<<rows, 256>>>(A, f1z, f2z, f1s, f2s, mz, iz, ms, is_, N_);

    // Z = relu(P_z @ Wh_z); S_pre = relu(P_s @ Wh_s) — P on the fly, tensor cores
    {
        dim3 g((Fz + 127) / 128, (N_ + 127) / 128, BATCH);
        mma_k<128, 128, AM_FUSED, true, false><<<g, 256>>>(A, whz, z, N_, Fz, N_,
            (long)N_ * N_, (long)N_ * Fz, (long)N_ * Fz, f1z, f2z, mz, iz);
    }
    {
        dim3 g((c + 63) / 64, (N_ + 127) / 128, BATCH);
        mma_k<128, 64, AM_FUSED, true, false><<<g, 256>>>(A, whs, s, N_, c, N_,
            (long)N_ * N_, (long)N_ * c, (long)N_ * c, f1s, f2s, ms, is_);
    }
    softmax_c_ent<<<(rows + 7) / 8, 256>>>(s, rows, c, 1.0 / (double)rows);

    // T = S^T A   (B = adjacency is exactly bf16 -> EXB)
    {
        dim3 g((N_ + 127) / 128, (c + 63) / 64, BATCH);
        mma_k<64, 128, AM_TN, false, true><<<g, 256>>>(s, A, t, c, N_, N_,
            (long)N_ * c, (long)N_ * N_, (long)c * N_, NOF);
    }
    // A_new = T @ S
    {
        dim3 g((c + 127) / 128, (c + 63) / 64, BATCH);
        mma_k<64, 128, AM_NN, false, false><<<g, 256>>>(t, s, Aout, c, c, N_,
            (long)c * N_, (long)N_ * c, (long)c * c, NOF);
    }
    // X_new = S^T Z
    {
        dim3 g((Fz + 127) / 128, (c + 63) / 64, BATCH);
        mma_k<64, 128, AM_TN, false, false><<<g, 256>>>(s, z, Xout, c, Fz, N_,
            (long)N_ * c, (long)N_ * Fz, (long)c * Fz, NOF);
    }
    // G = S^T S
    {
        dim3 g((c + 127) / 128, (c + 63) / 64, BATCH);
        mma_k<64, 128, AM_TN, false, false><<<g, 256>>>(s, s, gg, c, c, N_,
            (long)N_ * c, (long)N_ * c, (long)c * c, NOF);
    }

    // link loss: ||A - S S^T||_F^2 = sum(A^2) - 2 tr(S^T A S) + ||S^T S||_F^2
    trace_neg2<<<(BATCH * c + 255) / 256, 256>>>(Aout, BATCH * c, c);
    long nG = (long)BATCH * c * c;
    accum_sq<<<grid_for(nG), 256>>>(gg, nG);
    long nA = (long)BATCH * N_ * N_;
    k_finalize_link<<<1, 1>>>((double)nA);
}

extern "C" void kernel_launch(void* const* d_in, const int* in_sizes, int n_in,
                              void* d_out, int out_size)
{
    (void)in_sizes; (void)n_in;
    const float* X  = (const float*)d_in[0];
    const float* A  = (const float*)d_in[1];
    const float* Wg[3]  = {(const float*)d_in[2], (const float*)d_in[6],  (const float*)d_in[10]};
    const float* ag[3]  = {(const float*)d_in[3], (const float*)d_in[7],  (const float*)d_in[11]};
    const float* Ws[3]  = {(const float*)d_in[4], (const float*)d_in[8],  (const float*)d_in[12]};
    const float* as_[3] = {(const float*)d_in[5], (const float*)d_in[9],  (const float*)d_in[13]};
    const float* Wd = (const float*)d_in[14];
    const float* bd = (const float*)d_in[15];
    float* out = (float*)d_out;

    float *whz, *whs, *z, *s, *t, *gg;
    float *xp, *ap, *xq, *aq, *x3, *a3;
    float *f1z, *f2z, *f1s, *f2s, *mz, *iz, *ms, *is_;
    cudaGetSymbolAddress((void**)&whz, g_Whz);
    cudaGetSymbolAddress((void**)&whs, g_Whs);
    cudaGetSymbolAddress((void**)&z,   g_Zb);
    cudaGetSymbolAddress((void**)&s,   g_Sb);
    cudaGetSymbolAddress((void**)&t,   g_Tb);
    cudaGetSymbolAddress((void**)&gg,  g_Gb);
    cudaGetSymbolAddress((void**)&xp,  g_Xp);
    cudaGetSymbolAddress((void**)&ap,  g_Ap);
    cudaGetSymbolAddress((void**)&xq,  g_Xq);
    cudaGetSymbolAddress((void**)&aq,  g_Aq);
    cudaGetSymbolAddress((void**)&x3,  g_X3);
    cudaGetSymbolAddress((void**)&a3,  g_A3);
    cudaGetSymbolAddress((void**)&f1z, g_f1z);
    cudaGetSymbolAddress((void**)&f2z, g_f2z);
    cudaGetSymbolAddress((void**)&f1s, g_f1s);
    cudaGetSymbolAddress((void**)&f2s, g_f2s);
    cudaGetSymbolAddress((void**)&mz,  g_mz);
    cudaGetSymbolAddress((void**)&iz,  g_iz);
    cudaGetSymbolAddress((void**)&ms,  g_ms);
    cudaGetSymbolAddress((void**)&is_, g_is);

    k_zero_losses<<<1, 1>>>();

    // layer 0: N=1024, Fin=128, Fz=256, c=64
    run_layer(X, A, Wg[0], ag[0], Ws[0], as_[0], xp, ap,
              1024, 128, 256, 64, whz, whs, z, s, t, gg,
              f1z, f2z, f1s, f2s, mz, iz, ms, is_);
    // layer 1: N=64, Fin=256, Fz=256, c=8
    run_layer(xp, ap, Wg[1], ag[1], Ws[1], as_[1], xq, aq,
              64, 256, 256, 8, whz, whs, z, s, t, gg,
              f1z, f2z, f1s, f2s, mz, iz, ms, is_);
    // layer 2: N=8, Fin=256, Fz=256, c=1
    run_layer(xq, aq, Wg[2], ag[2], Ws[2], as_[2], x3, a3,
              8, 256, 256, 1, whz, whs, z, s, t, gg,
              f1z, f2z, f1s, f2s, mz, iz, ms, is_);

    final_logits<<<1, 192>>>(x3, Wd, bd, out, out_size);
    write_tail<<<1, 32>>>(a3, out, out_size);
}

// round 8
// speedup vs baseline: 2.5434x; 1.1252x over previous
#include <cuda_runtime.h>
#include <cuda_fp16.h>
#include <math.h>
#include <stdint.h>

#define BATCH 16
#define NCLASS 10

// ---------------- scratch (static __device__, allocation-free) ----------------
__device__ float g_Whz[(size_t)BATCH * 1024 * 256];
__device__ float g_Whs[(size_t)BATCH * 1024 * 64];
__device__ float g_Zb [(size_t)BATCH * 1024 * 256];
__device__ float g_Sb [(size_t)BATCH * 1024 * 64];
__device__ float g_Tb [(size_t)BATCH * 64 * 1024];
__device__ float g_Gb [(size_t)BATCH * 64 * 64];
__device__ float g_Xp [(size_t)BATCH * 64 * 256];
__device__ float g_Ap [(size_t)BATCH * 64 * 64];
__device__ float g_f1z[BATCH * 1024];
__device__ float g_f2z[BATCH * 1024];
__device__ float g_f1s[BATCH * 1024];
__device__ float g_f2s[BATCH * 1024];
__device__ float g_mz [BATCH * 1024];
__device__ float g_iz [BATCH * 1024];
__device__ float g_ms [BATCH * 1024];
__device__ float g_is [BATCH * 1024];
__device__ double g_link, g_ent, g_tot, g_tot1, g_tot2;

// pack two floats' fp16 hi/lo splits into half2 words
__device__ __forceinline__ void pack_split(float x0, float x1, uint32_t& hw, uint32_t& lw) {
    __half h0 = __float2half_rn(x0);
    __half h1 = __float2half_rn(x1);
    float r0 = x0 - __half2float(h0);
    float r1 = x1 - __half2float(h1);
    __half l0 = __float2half_rn(r0);
    __half l1 = __float2half_rn(r1);
    hw = (uint32_t)__half_as_ushort(h0) | ((uint32_t)__half_as_ushort(h1) << 16);
    lw = (uint32_t)__half_as_ushort(l0) | ((uint32_t)__half_as_ushort(l1) << 16);
}

#define AM_NN    0
#define AM_TN    1
#define AM_FUSED 2

// ---------------- 3xFP16 split warp-MMA GEMM (near-fp32 accurate) ----------------
// C[b] = op(A[b]) * B[b] via mma.sync.m16n8k16.f16 with hi/lo split:
//   C += Ahi*Bhi + Ahi*Blo + Alo*Bhi     (lo*lo dropped, ~2^-22 relative)
// EXB: B operand exactly fp16-representable (adjacency 0/1) -> skip Ahi*Blo.
template<int BM, int BN, int AM, bool RELU, bool EXB>
__global__ __launch_bounds__(256)
void mma_k(const float* __restrict__ Ag, const float* __restrict__ Bg,
           float* __restrict__ Cg, int M, int N, int K,
           long sA, long sB, long sC,
           const float* __restrict__ f1, const float* __restrict__ f2,
           const float* __restrict__ rm, const float* __restrict__ ri)
{
    constexpr int BK  = 16;
    constexpr int KP  = 8;
    constexpr int PAD = 8;
    constexpr int WM  = BM / 2;
    constexpr int WN  = BN / 4;
    constexpr int MT  = WM / 16;
    constexpr int NT  = WN / 8;
    constexpr int APL = (BM * KP) / 256;
    constexpr int BPL = (BN * KP) / 256;

    __shared__ uint32_t AsH[KP][BM + PAD];
    __shared__ uint32_t AsL[KP][BM + PAD];
    __shared__ uint32_t BsH[KP][BN + PAD];
    __shared__ uint32_t BsL[EXB ? 1 : KP][BN + PAD];
    __shared__ float s_f1[BM], s_m[BM], s_i[BM];

    const int b = blockIdx.z;
    const float* Ab = Ag + (long)b * sA;
    const float* Bb = Bg + (long)b * sB;
    float* Cb = Cg + (long)b * sC;

    const int bm = blockIdx.y * BM, bn = blockIdx.x * BN;
    const int tid  = threadIdx.x;
    const int warp = tid >> 5, lane = tid & 31;
    const int wm = (warp >> 2) * WM, wn = (warp & 3) * WN;
    const int lg = lane >> 2, lt = lane & 3;

    const float* f2b = nullptr;
    if (AM == AM_FUSED) {
        f2b = f2 + (long)b * K;
        const float* f1b = f1 + (long)b * K;
        const float* rmb = rm + (long)b * K;
        const float* rib = ri + (long)b * K;
        for (int i = tid; i < BM; i += 256) {
            int gi = bm + i;
            if (gi < M) { s_f1[i] = f1b[gi]; s_m[i] = rmb[gi]; s_i[i] = rib[gi]; }
            else        { s_f1[i] = 0.f; s_m[i] = 0.f; s_i[i] = 1.f; }
        }
    }

    float acc[MT][NT][4];
#pragma unroll
    for (int mt = 0; mt < MT; mt++)
#pragma unroll
        for (int nt = 0; nt < NT; nt++)
#pragma unroll
            for (int q = 0; q < 4; q++) acc[mt][nt][q] = 0.f;

    float2 rA[APL], rB[BPL];
    float2 rF[(AM == AM_FUSED) ? APL : 1];

    auto loadA = [&](int k0) {
#pragma unroll
        for (int t = 0; t < APL; t++) {
            int idx = tid + 256 * t;
            if (AM == AM_TN) {
                int m = idx % BM, kp = idx / BM;
                int gm = bm + m, gk = k0 + 2 * kp;
                float x0 = (gm < M && gk     < K) ? Ab[(long)gk * M + gm]       : 0.f;
                float x1 = (gm < M && gk + 1 < K) ? Ab[(long)(gk + 1) * M + gm] : 0.f;
                rA[t] = make_float2(x0, x1);
            } else {
                int kp = idx & 7, m = idx >> 3;
                int gm = bm + m, gk = k0 + 2 * kp;
                float x0 = 0.f, x1 = 0.f;
                if (gm < M) {
                    if (gk + 1 < K) {
                        float2 v = *reinterpret_cast<const float2*>(&Ab[(long)gm * K + gk]);
                        x0 = v.x; x1 = v.y;
                    } else if (gk < K) {
                        x0 = Ab[(long)gm * K + gk];
                    }
                }
                rA[t] = make_float2(x0, x1);
                if (AM == AM_FUSED) {
                    float fa = 0.f, fb = 0.f;
                    if (gk + 1 < K) {
                        float2 v = *reinterpret_cast<const float2*>(&f2b[gk]);
                        fa = v.x; fb = v.y;
                    } else if (gk < K) {
                        fa = f2b[gk];
                    }
                    rF[t] = make_float2(fa, fb);
                }
            }
        }
    };
    auto loadB = [&](int k0) {
#pragma unroll
        for (int t = 0; t < BPL; t++) {
            int idx = tid + 256 * t;
            int n = idx % BN, kp = idx / BN;
            int gn = bn + n, gk = k0 + 2 * kp;
            float x0 = (gn < N && gk     < K) ? Bb[(long)gk * N + gn]       : 0.f;
            float x1 = (gn < N && gk + 1 < K) ? Bb[(long)(gk + 1) * N + gn] : 0.f;
            rB[t] = make_float2(x0, x1);
        }
    };
    auto storeAB = [&](int k0) {
#pragma unroll
        for (int t = 0; t < APL; t++) {
            int idx = tid + 256 * t;
            int kp, m;
            if (AM == AM_TN) { m = idx % BM; kp = idx / BM; }
            else             { kp = idx & 7; m = idx >> 3; }
            float x0 = rA[t].x, x1 = rA[t].y;
            if (AM == AM_FUSED) {
                int gk = k0 + 2 * kp;
                float e0 = s_f1[m] + rF[t].x; e0 = (e0 > 0.f) ? e0 : 0.2f * e0;
                if (!(x0 > 0.f)) e0 = -9e15f;
                float e1 = s_f1[m] + rF[t].y; e1 = (e1 > 0.f) ? e1 : 0.2f * e1;
                if (!(x1 > 0.f)) e1 = -9e15f;
                x0 = (gk     < K) ? __expf(e0 - s_m[m]) * s_i[m] : 0.f;
                x1 = (gk + 1 < K) ? __expf(e1 - s_m[m]) * s_i[m] : 0.f;
            }
            uint32_t hw, lw; pack_split(x0, x1, hw, lw);
            AsH[kp][m] = hw; AsL[kp][m] = lw;
        }
#pragma unroll
        for (int t = 0; t < BPL; t++) {
            int idx = tid + 256 * t;
            int n = idx % BN, kp = idx / BN;
            uint32_t hw, lw; pack_split(rB[t].x, rB[t].y, hw, lw);
            BsH[kp][n] = hw;
            if (!EXB) BsL[kp][n] = lw;
        }
    };

    loadA(0); loadB(0);
    __syncthreads();

    for (int k0 = 0; k0 < K; k0 += BK) {
        storeAB(k0);
        __syncthreads();
        if (k0 + BK < K) { loadA(k0 + BK); loadB(k0 + BK); }

        uint32_t ah[MT][4], al[MT][4], bh[NT][2], bl[NT][2];
#pragma unroll
        for (int mt = 0; mt < MT; mt++) {
            int r = wm + mt * 16;
            ah[mt][0] = AsH[lt    ][r + lg];
            ah[mt][1] = AsH[lt    ][r + lg + 8];
            ah[mt][2] = AsH[lt + 4][r + lg];
            ah[mt][3] = AsH[lt + 4][r + lg + 8];
            al[mt][0] = AsL[lt    ][r + lg];
            al[mt][1] = AsL[lt    ][r + lg + 8];
            al[mt][2] = AsL[lt + 4][r + lg];
            al[mt][3] = AsL[lt + 4][r + lg + 8];
        }
#pragma unroll
        for (int nt = 0; nt < NT; nt++) {
            int cidx = wn + nt * 8 + lg;
            bh[nt][0] = BsH[lt    ][cidx];
            bh[nt][1] = BsH[lt + 4][cidx];
            if (!EXB) {
                bl[nt][0] = BsL[lt    ][cidx];
                bl[nt][1] = BsL[lt + 4][cidx];
            }
        }
#define MMA_STEP(AF, BF)                                                        \
        asm volatile(                                                           \
            "mma.sync.aligned.m16n8k16.row.col.f32.f16.f16.f32 "                \
            "{%0,%1,%2,%3}, {%4,%5,%6,%7}, {%8,%9}, {%0,%1,%2,%3};"             \
            : "+f"(acc[mt][nt][0]), "+f"(acc[mt][nt][1]),                       \
              "+f"(acc[mt][nt][2]), "+f"(acc[mt][nt][3])                        \
            : "r"(AF[mt][0]), "r"(AF[mt][1]), "r"(AF[mt][2]), "r"(AF[mt][3]),   \
              "r"(BF[nt][0]), "r"(BF[nt][1]))
#pragma unroll
        for (int mt = 0; mt < MT; mt++)
#pragma unroll
            for (int nt = 0; nt < NT; nt++) {
                if (!EXB) MMA_STEP(ah, bl);
                MMA_STEP(al, bh);
                MMA_STEP(ah, bh);
            }
#undef MMA_STEP
        __syncthreads();
    }

#pragma unroll
    for (int mt = 0; mt < MT; mt++) {
#pragma unroll
        for (int nt = 0; nt < NT; nt++) {
            int gm = bm + wm + mt * 16 + lg;
            int gn = bn + wn + nt * 8 + 2 * lt;
            float v0 = acc[mt][nt][0], v1 = acc[mt][nt][1];
            float v2 = acc[mt][nt][2], v3 = acc[mt][nt][3];
            if (RELU) {
                v0 = v0 > 0.f ? v0 : 0.f;  v1 = v1 > 0.f ? v1 : 0.f;
                v2 = v2 > 0.f ? v2 : 0.f;  v3 = v3 > 0.f ? v3 : 0.f;
            }
            if (gm < M) {
                if (gn     < N) Cb[(long)gm * N + gn    ] = v0;
                if (gn + 1 < N) Cb[(long)gm * N + gn + 1] = v1;
            }
            if (gm + 8 < M) {
                if (gn     < N) Cb[(long)(gm + 8) * N + gn    ] = v2;
                if (gn + 1 < N) Cb[(long)(gm + 8) * N + gn + 1] = v3;
            }
        }
    }
}

// ---------------- row stats (layer 0 only) ----------------
__global__ void rowstat_k(const float* __restrict__ A,
                          const float* __restrict__ f1z, const float* __restrict__ f2z,
                          const float* __restrict__ f1s, const float* __restrict__ f2s,
                          float* __restrict__ mz, float* __restrict__ iz,
                          float* __restrict__ ms, float* __restrict__ is_, int N)
{
    int row = blockIdx.x;
    int b = row / N;
    const float* Ar = A + (size_t)row * N;
    const float* f2zb = f2z + (size_t)b * N;
    const float* f2sb = f2s + (size_t)b * N;
    float fz = f1z[row], fs = f1s[row];
    int t = threadIdx.x;
    float ez[4], es[4];
    float mzl = -1e30f, msl = -1e30f;
    double ss = 0.0;
#pragma unroll
    for (int it = 0; it < 4; it++) {
        int j = t + it * 256;
        float vz = -9e15f, vs = -9e15f;
        if (j < N) {
            float a = Ar[j];
            ss += (double)a * (double)a;
            bool on = a > 0.f;
            float xz = fz + f2zb[j];
            float xs = fs + f2sb[j];
            float lz = (xz > 0.f) ? xz : 0.2f * xz;
            float ls = (xs > 0.f) ? xs : 0.2f * xs;
            vz = on ? lz : -9e15f;
            vs = on ? ls : -9e15f;
        }
        ez[it] = vz; es[it] = vs;
        mzl = fmaxf(mzl, vz); msl = fmaxf(msl, vs);
    }
    __shared__ float sh[256];
    sh[t] = mzl; __syncthreads();
    for (int s = 128; s > 0; s >>= 1) { if (t < s) sh[t] = fmaxf(sh[t], sh[t + s]); __syncthreads(); }
    float Mz = sh[0]; __syncthreads();
    sh[t] = msl; __syncthreads();
    for (int s = 128; s > 0; s >>= 1) { if (t < s) sh[t] = fmaxf(sh[t], sh[t + s]); __syncthreads(); }
    float Ms = sh[0]; __syncthreads();

    float sz = 0.f, ssum = 0.f;
#pragma unroll
    for (int it = 0; it < 4; it++) {
        int j = t + it * 256;
        if (j < N) { sz += __expf(ez[it] - Mz); ssum += __expf(es[it] - Ms); }
    }
    sh[t] = sz; __syncthreads();
    for (int s = 128; s > 0; s >>= 1) { if (t < s) sh[t] += sh[t + s]; __syncthreads(); }
    float Sz = sh[0]; __syncthreads();
    sh[t] = ssum; __syncthreads();
    for (int s = 128; s > 0; s >>= 1) { if (t < s) sh[t] += sh[t + s]; __syncthreads(); }
    float Ss = sh[0]; __syncthreads();

    __shared__ double dh[256];
    dh[t] = ss; __syncthreads();
    for (int s = 128; s > 0; s >>= 1) { if (t < s) dh[t] += dh[t + s]; __syncthreads(); }

    if (t == 0) {
        mz[row] = Mz; iz[row] = 1.f / Sz;
        ms[row] = Ms; is_[row] = 1.f / Ss;
        atomicAdd(&g_tot, dh[0]);
    }
}

// ---------------- f1/f2 (warp per row) ----------------
__global__ void fvec_k(const float* __restrict__ Wh, const float* __restrict__ a,
                       float* __restrict__ f1, float* __restrict__ f2,
                       int rows, int F)
{
    int w = (blockIdx.x * blockDim.x + threadIdx.x) >> 5;
    int lane = threadIdx.x & 31;
    if (w >= rows) return;
    const float* p = Wh + (size_t)w * F;
    float s1 = 0.f, s2 = 0.f;
    for (int f = lane; f < F; f += 32) {
        float v = p[f];
        s1 += v * a[f];
        s2 += v * a[F + f];
    }
#pragma unroll
    for (int o = 16; o > 0; o >>= 1) {
        s1 += __shfl_down_sync(0xffffffffu, s1, o);
        s2 += __shfl_down_sync(0xffffffffu, s2, o);
    }
    if (lane == 0) { f1[w] = s1; f2[w] = s2; }
}

// ---------------- softmax over c + entropy (layer 0) ----------------
__global__ void softmax_c_ent(float* __restrict__ S, int rows, int c, double inv_rows)
{
    int w = (blockIdx.x * blockDim.x + threadIdx.x) >> 5;
    int lane = threadIdx.x & 31;
    if (w >= rows) return;
    float* p = S + (size_t)w * c;
    float v[2] = {-1e30f, -1e30f};
    float m = -1e30f;
#pragma unroll
    for (int i = 0; i < 2; i++) {
        int f = lane + 32 * i;
        if (f < c) { v[i] = p[f]; m = fmaxf(m, v[i]); }
    }
#pragma unroll
    for (int o = 16; o > 0; o >>= 1) m = fmaxf(m, __shfl_xor_sync(0xffffffffu, m, o));
    float s = 0.f;
#pragma unroll
    for (int i = 0; i < 2; i++) {
        int f = lane + 32 * i;
        if (f < c) { v[i] = __expf(v[i] - m); s += v[i]; }
    }
#pragma unroll
    for (int o = 16; o > 0; o >>= 1) s += __shfl_xor_sync(0xffffffffu, s, o);
    float inv = 1.f / s;
    double erow = 0.0;
#pragma unroll
    for (int i = 0; i < 2; i++) {
        int f = lane + 32 * i;
        if (f < c) {
            float q = v[i] * inv;
            p[f] = q;
            erow += -(double)q * (double)logf(q + 1e-15f);
        }
    }
#pragma unroll
    for (int o = 16; o > 0; o >>= 1) erow += __shfl_down_sync(0xffffffffu, erow, o);
    if (lane == 0) atomicAdd(&g_ent, erow * inv_rows);
}

// ---------------- layer-0 link loss finalize ----------------
__global__ void link0_fin(const float* __restrict__ Ap, const float* __restrict__ G)
{
    int t = threadIdx.x;
    double s = 0.0;
    for (int idx = t; idx < BATCH * 64; idx += 256) {
        int b = idx / 64, j = idx % 64;
        s += -2.0 * (double)Ap[((long)b * 64 + j) * 64 + j];
    }
    for (int idx = t; idx < BATCH * 64 * 64; idx += 256) {
        double g = G[idx]; s += g * g;
    }
    __shared__ double sh[256];
    sh[t] = s; __syncthreads();
    for (int r = 128; r > 0; r >>= 1) { if (t < r) sh[t] += sh[t + r]; __syncthreads(); }
    if (t == 0) {
        double v = g_tot + sh[0];
        g_link += sqrt(v > 0.0 ? v : 0.0) / (double)((long)BATCH * 1024 * 1024);
    }
}

__global__ void k_zero_losses() { g_link = 0.0; g_ent = 0.0; g_tot = 0.0; g_tot1 = 0.0; g_tot2 = 0.0; }

// ---------------- fused layers 1+2 tail (fp32, one block per batch) ----------------
// SMEM budget (floats): see offsets below; total 49576, allocate 49664.
#define FUSED_SMEM_FLOATS 49664

__global__ __launch_bounds__(256)
void fused_tail_k(const float* __restrict__ Whz1g, const float* __restrict__ Whs1g,
                  const float* __restrict__ A1g,
                  const float* __restrict__ f1zg, const float* __restrict__ f2zg,
                  const float* __restrict__ f1sg, const float* __restrict__ f2sg,
                  const float* __restrict__ Wg2, const float* __restrict__ ag2,
                  const float* __restrict__ Ws2, const float* __restrict__ as2,
                  const float* __restrict__ Wd, const float* __restrict__ bd,
                  float* __restrict__ out, int out_size)
{
    const int b = blockIdx.x, tid = threadIdx.x;
    const int warp = tid >> 5, lane = tid & 31;
    extern __shared__ float sm[];
    float* sWh  = sm;              // +16384 -> 16384
    float* sZ   = sWh  + 16384;    // +16384 -> 32768
    float* sA   = sZ   + 16384;    // +4096  -> 36864
    float* sE   = sA   + 4096;     // +4096  -> 40960
    float* sX2  = sE   + 4096;     // +2048  -> 43008
    float* sWh2 = sX2  + 2048;     // +2048  -> 45056
    float* sZ2  = sWh2 + 2048;     // +2048  -> 47104
    float* sWhs = sZ2  + 2048;     // +512   -> 47616
    float* sS   = sWhs + 512;      // +512   -> 48128
    float* sT   = sS   + 512;      // +512   -> 48640
    float* sf1  = sT   + 512;      // +64
    float* sf2  = sf1  + 64;       // +64
    float* sg1  = sf2  + 64;       // +64
    float* sg2  = sg1  + 64;       // +64
    float* sA2  = sg2  + 64;       // +64    -> 48960
    float* sX3  = sA2  + 64;       // +256   -> 49216
    float* sWhs2= sX3  + 256;      // +8
    float* sP2  = sWhs2+ 8;        // +64
    float* sf1b = sP2  + 64;       // +8
    float* sf2b = sf1b + 8;        // +8
    float* sf1c = sf2b + 8;        // +8
    float* sf2c = sf1c + 8;        // +8     -> 49320
    float* sred = sf2c + 8;        // +256   -> 49576 total

    // ---- loads ----
    for (int i = tid; i < 64 * 256; i += 256) sWh[i] = Whz1g[(size_t)b * 16384 + i];
    for (int i = tid; i < 4096; i += 256)     sA[i]  = A1g [(size_t)b * 4096 + i];
    for (int i = tid; i < 512; i += 256)      sWhs[i] = Whs1g[(size_t)b * 512 + i];
    if (tid < 64) {
        sf1[tid] = f1zg[b * 64 + tid]; sf2[tid] = f2zg[b * 64 + tid];
        sg1[tid] = f1sg[b * 64 + tid]; sg2[tid] = f2sg[b * 64 + tid];
    }
    __syncthreads();

    // ---- layer-1 attention (z), warp per row ----
    for (int r = warp * 8; r < warp * 8 + 8; r++) {
        float f1i = sf1[r];
        float e0, e1;
        {
            int j = lane;
            float x = f1i + sf2[j]; x = (x > 0.f) ? x : 0.2f * x;
            e0 = (sA[r * 64 + j] > 0.f) ? x : -9e15f;
            j = lane + 32;
            x = f1i + sf2[j]; x = (x > 0.f) ? x : 0.2f * x;
            e1 = (sA[r * 64 + j] > 0.f) ? x : -9e15f;
        }
        float m = fmaxf(e0, e1);
#pragma unroll
        for (int o = 16; o > 0; o >>= 1) m = fmaxf(m, __shfl_xor_sync(0xffffffffu, m, o));
        float p0 = __expf(e0 - m), p1 = __expf(e1 - m);
        float s = p0 + p1;
#pragma unroll
        for (int o = 16; o > 0; o >>= 1) s += __shfl_xor_sync(0xffffffffu, s, o);
        float inv = 1.f / s;
        sE[r * 64 + lane] = p0 * inv;
        sE[r * 64 + lane + 32] = p1 * inv;
    }
    __syncthreads();

    // ---- Z1 = relu(Pz @ Whz1)  [64x256], col per thread ----
    for (int n0 = 0; n0 < 64; n0 += 16) {
        float acc[16];
#pragma unroll
        for (int i = 0; i < 16; i++) acc[i] = 0.f;
        for (int k = 0; k < 64; k++) {
            float whv = sWh[k * 256 + tid];
#pragma unroll
            for (int i = 0; i < 16; i++) acc[i] += sE[(n0 + i) * 64 + k] * whv;
        }
#pragma unroll
        for (int i = 0; i < 16; i++) sZ[(n0 + i) * 256 + tid] = fmaxf(acc[i], 0.f);
    }
    __syncthreads();

    // ---- layer-1 attention (s) into sE ----
    for (int r = warp * 8; r < warp * 8 + 8; r++) {
        float f1i = sg1[r];
        float e0, e1;
        {
            int j = lane;
            float x = f1i + sg2[j]; x = (x > 0.f) ? x : 0.2f * x;
            e0 = (sA[r * 64 + j] > 0.f) ? x : -9e15f;
            j = lane + 32;
            x = f1i + sg2[j]; x = (x > 0.f) ? x : 0.2f * x;
            e1 = (sA[r * 64 + j] > 0.f) ? x : -9e15f;
        }
        float m = fmaxf(e0, e1);
#pragma unroll
        for (int o = 16; o > 0; o >>= 1) m = fmaxf(m, __shfl_xor_sync(0xffffffffu, m, o));
        float p0 = __expf(e0 - m), p1 = __expf(e1 - m);
        float s = p0 + p1;
#pragma unroll
        for (int o = 16; o > 0; o >>= 1) s += __shfl_xor_sync(0xffffffffu, s, o);
        float inv = 1.f / s;
        sE[r * 64 + lane] = p0 * inv;
        sE[r * 64 + lane + 32] = p1 * inv;
    }
    __syncthreads();

    // ---- S1_pre = relu(Ps @ Whs1) [64x8] ----
    for (int idx = tid; idx < 512; idx += 256) {
        int n = idx >> 3, cc = idx & 7;
        float s = 0.f;
        for (int j = 0; j < 64; j++) s += sE[n * 64 + j] * sWhs[j * 8 + cc];
        sS[idx] = fmaxf(s, 0.f);
    }
    __syncthreads();

    // ---- softmax over c=8 + entropy ----
    if (tid < 64) {
        float v[8]; float m = -1e30f;
#pragma unroll
        for (int c = 0; c < 8; c++) { v[c] = sS[tid * 8 + c]; m = fmaxf(m, v[c]); }
        float s = 0.f;
#pragma unroll
        for (int c = 0; c < 8; c++) { v[c] = __expf(v[c] - m); s += v[c]; }
        float inv = 1.f / s;
        float ent = 0.f;
#pragma unroll
        for (int c = 0; c < 8; c++) {
            float q = v[c] * inv;
            sS[tid * 8 + c] = q;
            ent += -q * logf(q + 1e-15f);
        }
        sred[tid] = ent;
    }
    __syncthreads();
    if (tid == 0) {
        double e = 0.0;
        for (int i = 0; i < 64; i++) e += (double)sred[i];
        atomicAdd(&g_ent, e / 1024.0);
    }

    // ---- X2 = S1^T Z1 [8x256] ----
    for (int idx = tid; idx < 2048; idx += 256) {
        int c = idx >> 8, f = idx & 255;
        float s = 0.f;
        for (int n = 0; n < 64; n++) s += sS[n * 8 + c] * sZ[n * 256 + f];
        sX2[idx] = s;
    }
    // ---- T1 = S1^T A1 [8x64] ----
    for (int idx = tid; idx < 512; idx += 256) {
        int c = idx >> 6, j = idx & 63;
        float s = 0.f;
        for (int n = 0; n < 64; n++) s += sS[n * 8 + c] * sA[n * 64 + j];
        sT[idx] = s;
    }
    __syncthreads();
    // ---- A2 = T1 @ S1 [8x8] ----
    if (tid < 64) {
        int c = tid >> 3, d = tid & 7;
        float s = 0.f;
        for (int j = 0; j < 64; j++) s += sT[c * 64 + j] * sS[j * 8 + d];
        sA2[tid] = s;
    }
    // ---- link1: sum (A1 - S1 S1^T)^2 ----
    {
        float lsum = 0.f;
        for (int idx = tid; idx < 4096; idx += 256) {
            int i = idx >> 6, j = idx & 63;
            float d = 0.f;
#pragma unroll
            for (int c = 0; c < 8; c++) d += sS[i * 8 + c] * sS[j * 8 + c];
            float df = sA[idx] - d;
            lsum += df * df;
        }
        sred[tid] = lsum; __syncthreads();
        for (int r = 128; r > 0; r >>= 1) { if (tid < r) sred[tid] += sred[tid + r]; __syncthreads(); }
        if (tid == 0) atomicAdd(&g_tot1, (double)sred[0]);
    }
    __syncthreads();

    // ================= layer 2 (N=8, Fin=256, Fz=256, c=1) =================
    {
        float acc[8];
#pragma unroll
        for (int i = 0; i < 8; i++) acc[i] = 0.f;
        for (int k = 0; k < 256; k++) {
            float wg = Wg2[k * 256 + tid];
#pragma unroll
            for (int n = 0; n < 8; n++) acc[n] += sX2[n * 256 + k] * wg;
        }
#pragma unroll
        for (int n = 0; n < 8; n++) sWh2[n * 256 + tid] = acc[n];
    }
    {
        float p = 0.f;
        for (int k = lane; k < 256; k += 32) p += sX2[warp * 256 + k] * Ws2[k];
#pragma unroll
        for (int o = 16; o > 0; o >>= 1) p += __shfl_down_sync(0xffffffffu, p, o);
        if (lane == 0) sWhs2[warp] = p;
    }
    __syncthreads();
    {
        float p1 = 0.f, p2 = 0.f;
        for (int k = lane; k < 256; k += 32) {
            float v = sWh2[warp * 256 + k];
            p1 += v * ag2[k];
            p2 += v * ag2[256 + k];
        }
#pragma unroll
        for (int o = 16; o > 0; o >>= 1) {
            p1 += __shfl_down_sync(0xffffffffu, p1, o);
            p2 += __shfl_down_sync(0xffffffffu, p2, o);
        }
        if (lane == 0) { sf1b[warp] = p1; sf2b[warp] = p2; }
    }
    if (tid < 8) {
        sf1c[tid] = sWhs2[tid] * as2[0];
        sf2c[tid] = sWhs2[tid] * as2[1];
    }
    __syncthreads();
    if (tid < 8) {
        float e[8]; float m = -1e30f;
#pragma unroll
        for (int j = 0; j < 8; j++) {
            float x = sf1b[tid] + sf2b[j]; x = (x > 0.f) ? x : 0.2f * x;
            e[j] = (sA2[tid * 8 + j] > 0.f) ? x : -9e15f;
            m = fmaxf(m, e[j]);
        }
        float s = 0.f;
#pragma unroll
        for (int j = 0; j < 8; j++) { e[j] = __expf(e[j] - m); s += e[j]; }
        float inv = 1.f / s;
#pragma unroll
        for (int j = 0; j < 8; j++) sP2[tid * 8 + j] = e[j] * inv;
    }
    __syncthreads();
    {
#pragma unroll
        for (int n = 0; n < 8; n++) {
            float z = 0.f;
#pragma unroll
            for (int k = 0; k < 8; k++) z += sP2[n * 8 + k] * sWh2[k * 256 + tid];
            sZ2[n * 256 + tid] = fmaxf(z, 0.f);
        }
    }
    __syncthreads();
    // S2 over c=1 is all-ones; ent2 == 0. X3 = column sums of Z2.
    {
        float s = 0.f;
#pragma unroll
        for (int n = 0; n < 8; n++) s += sZ2[n * 256 + tid];
        sX3[tid] = s;
    }
    if (tid < 64) {
        float d = sA2[tid] - 1.f;
        sred[tid] = d * d;
    } else sred[tid] = 0.f;
    __syncthreads();
    for (int r = 128; r > 0; r >>= 1) { if (tid < r) sred[tid] += sred[tid + r]; __syncthreads(); }
    if (tid == 0) {
        atomicAdd(&g_tot2, (double)sred[0]);
        float a3 = 0.f;
        for (int i = 0; i < 64; i++) a3 += sA2[i];
        if (160 + b < out_size) out[160 + b] = a3;
    }
    __syncthreads();
    if (tid < NCLASS) {
        float v = bd[tid];
        for (int f = 0; f < 256; f++) v += sX3[f] * Wd[f * NCLASS + tid];
        if (b * NCLASS + tid < out_size) out[b * NCLASS + tid] = v;
    }
}

// ---------------- final: write losses ----------------
__global__ void tail_fin(float* __restrict__ out, int out_size)
{
    if (threadIdx.x == 0) {
        double t1 = g_tot1, t2 = g_tot2;
        double link = g_link
                    + sqrt(t1 > 0.0 ? t1 : 0.0) / 65536.0
                    + sqrt(t2 > 0.0 ? t2 : 0.0) / 1024.0;
        if (176 < out_size) out[176] = (float)link;
        if (177 < out_size) out[177] = (float)g_ent;
    }
}

#define NOF nullptr, nullptr, nullptr, nullptr

extern "C" void kernel_launch(void* const* d_in, const int* in_sizes, int n_in,
                              void* d_out, int out_size)
{
    (void)in_sizes; (void)n_in;
    const float* X  = (const float*)d_in[0];
    const float* A  = (const float*)d_in[1];
    const float* Wg0 = (const float*)d_in[2];
    const float* ag0 = (const float*)d_in[3];
    const float* Ws0 = (const float*)d_in[4];
    const float* as0 = (const float*)d_in[5];
    const float* Wg1 = (const float*)d_in[6];
    const float* ag1 = (const float*)d_in[7];
    const float* Ws1 = (const float*)d_in[8];
    const float* as1 = (const float*)d_in[9];
    const float* Wg2 = (const float*)d_in[10];
    const float* ag2 = (const float*)d_in[11];
    const float* Ws2 = (const float*)d_in[12];
    const float* as2 = (const float*)d_in[13];
    const float* Wd = (const float*)d_in[14];
    const float* bd = (const float*)d_in[15];
    float* out = (float*)d_out;

    float *whz, *whs, *z, *s, *t, *gg, *xp, *ap;
    float *f1z, *f2z, *f1s, *f2s, *mz, *iz, *ms, *is_;
    cudaGetSymbolAddress((void**)&whz, g_Whz);
    cudaGetSymbolAddress((void**)&whs, g_Whs);
    cudaGetSymbolAddress((void**)&z,   g_Zb);
    cudaGetSymbolAddress((void**)&s,   g_Sb);
    cudaGetSymbolAddress((void**)&t,   g_Tb);
    cudaGetSymbolAddress((void**)&gg,  g_Gb);
    cudaGetSymbolAddress((void**)&xp,  g_Xp);
    cudaGetSymbolAddress((void**)&ap,  g_Ap);
    cudaGetSymbolAddress((void**)&f1z, g_f1z);
    cudaGetSymbolAddress((void**)&f2z, g_f2z);
    cudaGetSymbolAddress((void**)&f1s, g_f1s);
    cudaGetSymbolAddress((void**)&f2s, g_f2s);
    cudaGetSymbolAddress((void**)&mz,  g_mz);
    cudaGetSymbolAddress((void**)&iz,  g_iz);
    cudaGetSymbolAddress((void**)&ms,  g_ms);
    cudaGetSymbolAddress((void**)&is_, g_is);

    static bool attr_set = false;
    const int FUSED_SMEM = FUSED_SMEM_FLOATS * (int)sizeof(float);   // 198656 B
    if (!attr_set) {
        cudaFuncSetAttribute(fused_tail_k, cudaFuncAttributeMaxDynamicSharedMemorySize, FUSED_SMEM);
        attr_set = true;
    }

    k_zero_losses<<<1, 1>>>();

    // ================= layer 0: N=1024, Fin=128, Fz=256, c=64 =================
    const int N0 = 1024;
    {   // Wh_z = X @ Wg0
        dim3 g(2, 8, BATCH);
        mma_k<128, 128, AM_NN, false, false><<<g, 256>>>(X, Wg0, whz, N0, 256, 128,
            (long)N0 * 128, 0, (long)N0 * 256, NOF);
    }
    {   // Wh_s = X @ Ws0
        dim3 g(1, 8, BATCH);
        mma_k<128, 64, AM_NN, false, false><<<g, 256>>>(X, Ws0, whs, N0, 64, 128,
            (long)N0 * 128, 0, (long)N0 * 64, NOF);
    }
    {
        int rows = BATCH * N0;
        int fblocks = (rows * 32 + 255) / 256;
        fvec_k<<<fblocks, 256>>>(whz, ag0, f1z, f2z, rows, 256);
        fvec_k<<<fblocks, 256>>>(whs, as0, f1s, f2s, rows, 64);
        rowstat_k<<<rows, 256>>>(A, f1z, f2z, f1s, f2s, mz, iz, ms, is_, N0);
    }
    {   // Z = relu(Pz @ Whz)
        dim3 g(2, 8, BATCH);
        mma_k<128, 128, AM_FUSED, true, false><<<g, 256>>>(A, whz, z, N0, 256, N0,
            (long)N0 * N0, (long)N0 * 256, (long)N0 * 256, f1z, f2z, mz, iz);
    }
    {   // S_pre = relu(Ps @ Whs)
        dim3 g(1, 8, BATCH);
        mma_k<128, 64, AM_FUSED, true, false><<<g, 256>>>(A, whs, s, N0, 64, N0,
            (long)N0 * N0, (long)N0 * 64, (long)N0 * 64, f1s, f2s, ms, is_);
    }
    softmax_c_ent<<<(BATCH * N0 + 7) / 8, 256>>>(s, BATCH * N0, 64, 1.0 / (double)(BATCH * N0));
    {   // T = S^T A (EXB: A exactly fp16)
        dim3 g(8, 1, BATCH);
        mma_k<64, 128, AM_TN, false, true><<<g, 256>>>(s, A, t, 64, N0, N0,
            (long)N0 * 64, (long)N0 * N0, (long)64 * N0, NOF);
    }
    {   // A1 = T @ S
        dim3 g(1, 1, BATCH);
        mma_k<64, 128, AM_NN, false, false><<<g, 256>>>(t, s, ap, 64, 64, N0,
            (long)64 * N0, (long)N0 * 64, (long)64 * 64, NOF);
    }
    {   // X1 = S^T Z
        dim3 g(2, 1, BATCH);
        mma_k<64, 128, AM_TN, false, false><<<g, 256>>>(s, z, xp, 64, 256, N0,
            (long)N0 * 64, (long)N0 * 256, (long)64 * 256, NOF);
    }
    {   // G = S^T S
        dim3 g(1, 1, BATCH);
        mma_k<64, 128, AM_TN, false, false><<<g, 256>>>(s, s, gg, 64, 64, N0,
            (long)N0 * 64, (long)N0 * 64, (long)64 * 64, NOF);
    }
    link0_fin<<<1, 256>>>(ap, gg);

    // ================= layer 1 front (GEMMs + fvec), rest fused =================
    {   // Whz1 = X1 @ Wg1 [64x256 per batch]
        dim3 g(2, 1, BATCH);
        mma_k<128, 128, AM_NN, false, false><<<g, 256>>>(xp, Wg1, whz, 64, 256, 256,
            (long)64 * 256, 0, (long)64 * 256, NOF);
    }
    {   // Whs1 = X1 @ Ws1 [64x8]
        dim3 g(1, 1, BATCH);
        mma_k<128, 64, AM_NN, false, false><<<g, 256>>>(xp, Ws1, whs, 64, 8, 256,
            (long)64 * 256, 0, (long)64 * 8, NOF);
    }
    {
        int rows = BATCH * 64;
        int fblocks = (rows * 32 + 255) / 256;
        fvec_k<<<fblocks, 256>>>(whz, ag1, f1z, f2z, rows, 256);
        fvec_k<<<fblocks, 256>>>(whs, as1, f1s, f2s, rows, 8);
    }
    fused_tail_k<<<BATCH, 256, FUSED_SMEM>>>(whz, whs, ap, f1z, f2z, f1s, f2s,
                                             Wg2, ag2, Ws2, as2, Wd, bd, out, out_size);
    tail_fin<<<1, 32>>>(out, out_size);
}